// round 1
// baseline (speedup 1.0000x reference)
#include <cuda_runtime.h>
#include <cuda_bf16.h>
#include <math.h>

// ---------------- problem constants ----------------
#define BB 4
#define LL 2048
#define DD 512
#define DRR 256
#define RR 3
#define PP 5
#define PHH 3
#define FF 1536
#define NTOK (BB*LL)            // 8192
#define RDR (RR*DRR)            // 768

// ---------------- scratch layout (floats) ----------------
#define OFF_RES    0ULL
#define OFF_XN     4194304ULL
#define OFF_H      8388608ULL
#define OFF_DELTA  20971520ULL
#define OFF_SC     25165824ULL   // 8192
#define OFF_PART   25174016ULL   // 65536
#define OFF_Q      25239552ULL   // 512
#define OFF_KQ     25240064ULL   // 512
#define OFF_WXM    25240576ULL   // 512
#define OFF_SUMM   25241088ULL   // 512
#define OFF_REGS   25241600ULL   // 768   (gin = [regs | summary] contiguous)
#define OFF_SUMRY  25242368ULL   // 512
#define OFF_GATE   25242880ULL   // 512
#define OFF_WG     25243392ULL   // 16
#define OFF_BANKS  25243408ULL   // 3840
#define OFF_PW     25247248ULL   // 16
#define OFF_WXB    25247264ULL   // 2048
#define OFF_MS1    25249312ULL   // 2048
#define OFF_MO     25251360ULL   // 2048
#define SCRATCH_TOTAL 25253408ULL

__device__ __align__(256) float g_scratch[SCRATCH_TOTAL];

// ---------------- small kernels ----------------

__global__ void copy_kernel(const float* __restrict__ src, float* __restrict__ dst) {
    size_t i = (size_t)blockIdx.x * blockDim.x + threadIdx.x;
    dst[i] = src[i];
}

// pass_w[p] = sigmoid( sum_i tile(reg_init,5)[i] * ms3_w[i,p] + ms3_b[p] )
__global__ void passw_kernel(const float* __restrict__ reg_init,
                             const float* __restrict__ W,
                             const float* __restrict__ b,
                             float* __restrict__ pw) {
    int p = threadIdx.x;
    if (p >= PP) return;
    float acc = 0.f;
    for (int i = 0; i < PP * RDR; i++)
        acc += reg_init[i % RDR] * W[i * PP + p];
    pw[p] = 1.f / (1.f + expf(-(acc + b[p])));
}

// q[d] = sum_{i<n} bank[i] * Wq[i*512 + d]
__global__ void qproj_kernel(const float* __restrict__ bank, int n,
                             const float* __restrict__ Wq, float* __restrict__ q) {
    int d = blockIdx.x * blockDim.x + threadIdx.x;
    if (d >= DD) return;
    float acc = 0.f;
    for (int i = 0; i < n; i++)
        acc += bank[i] * Wq[(size_t)i * DD + d];
    q[d] = acc;
}

// out[r] = dot(M[r,:], v)  (M row-major 512x512)
__global__ void matvec_kernel(const float* __restrict__ M,
                              const float* __restrict__ v,
                              float* __restrict__ out) {
    __shared__ float red[128];
    int r = blockIdx.x;
    int tid = threadIdx.x;
    float acc = 0.f;
    for (int j = tid; j < DD; j += 128)
        acc += M[(size_t)r * DD + j] * v[j];
    red[tid] = acc; __syncthreads();
    for (int o = 64; o > 0; o >>= 1) {
        if (tid < o) red[tid] += red[tid + o];
        __syncthreads();
    }
    if (tid == 0) out[r] = red[0];
}

// out[j] = act( init[j] + sum_d v[d]*M[d*ncol+j] + bias[j] )   act: 0 none, 1 sigmoid
__global__ void vecmat_kernel(const float* __restrict__ v, const float* __restrict__ M,
                              const float* __restrict__ bias, const float* __restrict__ init,
                              float* __restrict__ out, int nrow, int ncol, int act) {
    int j = blockIdx.x * blockDim.x + threadIdx.x;
    if (j >= ncol) return;
    float acc = 0.f;
    for (int d = 0; d < nrow; d++)
        acc += v[d] * M[(size_t)d * ncol + j];
    if (bias) acc += bias[j];
    if (init) acc += init[j];
    if (act == 1) acc = 1.f / (1.f + expf(-acc));
    out[j] = acc;
}

// LayerNorm over D=512 per token; optionally emits score[t] = dot(xn, kq) * D^-0.5
__global__ void ln_kernel(const float* __restrict__ in, float* __restrict__ out,
                          const float* __restrict__ gs, const float* __restrict__ gb,
                          const float* __restrict__ kq, float* __restrict__ score) {
    __shared__ float red[256];
    int t = blockIdx.x;
    int tid = threadIdx.x;
    const float* row = in + (size_t)t * DD;
    float x0 = row[tid];
    float x1 = row[tid + 256];
    red[tid] = x0 + x1; __syncthreads();
    #pragma unroll
    for (int o = 128; o > 0; o >>= 1) { if (tid < o) red[tid] += red[tid + o]; __syncthreads(); }
    float mean = red[0] * (1.0f / 512.0f);
    __syncthreads();
    float d0 = x0 - mean, d1 = x1 - mean;
    red[tid] = d0 * d0 + d1 * d1; __syncthreads();
    #pragma unroll
    for (int o = 128; o > 0; o >>= 1) { if (tid < o) red[tid] += red[tid + o]; __syncthreads(); }
    float rstd = rsqrtf(red[0] * (1.0f / 512.0f) + 1e-5f);
    __syncthreads();
    float y0 = d0 * rstd * gs[tid] + gb[tid];
    float y1 = d1 * rstd * gs[tid + 256] + gb[tid + 256];
    out[(size_t)t * DD + tid] = y0;
    out[(size_t)t * DD + tid + 256] = y1;
    if (kq) {
        red[tid] = y0 * kq[tid] + y1 * kq[tid + 256]; __syncthreads();
        #pragma unroll
        for (int o = 128; o > 0; o >>= 1) { if (tid < o) red[tid] += red[tid + o]; __syncthreads(); }
        if (tid == 0) score[t] = red[0] * 0.044194173824159216f;  // 512^-0.5
    }
}

// softmax over L=2048 per batch (in place)
__global__ void softmax_kernel(float* __restrict__ sc) {
    __shared__ float red[1024];
    int b = blockIdx.x;
    float* p = sc + (size_t)b * LL;
    int tid = threadIdx.x;
    float v0 = p[tid], v1 = p[tid + 1024];
    red[tid] = fmaxf(v0, v1); __syncthreads();
    #pragma unroll
    for (int o = 512; o > 0; o >>= 1) { if (tid < o) red[tid] = fmaxf(red[tid], red[tid + o]); __syncthreads(); }
    float mx = red[0];
    __syncthreads();
    float e0 = expf(v0 - mx), e1 = expf(v1 - mx);
    red[tid] = e0 + e1; __syncthreads();
    #pragma unroll
    for (int o = 512; o > 0; o >>= 1) { if (tid < o) red[tid] += red[tid + o]; __syncthreads(); }
    float inv = 1.f / red[0];
    p[tid] = e0 * inv;
    p[tid + 1024] = e1 * inv;
}

// part[blk*512+d] = sum over 64 token rows of a[t]*xn[t,d]   (blk = 0..127, 64 | 2048)
__global__ void wxpart_kernel(const float* __restrict__ a, const float* __restrict__ xn,
                              float* __restrict__ part) {
    int d = threadIdx.x;
    int blk = blockIdx.x;
    int row0 = blk * 64;
    float acc = 0.f;
    for (int r = row0; r < row0 + 64; r++)
        acc += a[r] * xn[(size_t)r * DD + d];
    part[(size_t)blk * DD + d] = acc;
}

// part[c*512+d] = column-partial sum of delta rows [c*64, c*64+64)
__global__ void colsum_part_kernel(const float* __restrict__ delta, float* __restrict__ part) {
    int d = threadIdx.x;
    int c = blockIdx.x;
    float acc = 0.f;
    for (int r = c * 64; r < (c + 1) * 64; r++)
        acc += delta[(size_t)r * DD + d];
    part[(size_t)c * DD + d] = acc;
}

// out[g*512+d] = scale * sum_{c<nchunk} part[(g*nchunk+c)*512+d]
__global__ void part_reduce_kernel(const float* __restrict__ part, float* __restrict__ out,
                                   int nchunk, float scale) {
    int d = threadIdx.x;
    int g = blockIdx.x;
    const float* p = part + (size_t)g * nchunk * DD;
    float acc = 0.f;
    for (int c = 0; c < nchunk; c++)
        acc += p[(size_t)c * DD + d];
    out[(size_t)g * DD + d] = acc * scale;
}

// residual += pw[p] * gate[d] * delta
__global__ void resupd_kernel(float* __restrict__ res, const float* __restrict__ delta,
                              const float* __restrict__ gate, const float* __restrict__ pw, int p) {
    size_t i = (size_t)blockIdx.x * blockDim.x + threadIdx.x;
    res[i] += pw[p] * gate[i & 511] * delta[i];
}

// wg[r] = sigmoid( dot(summary, W[r,:]) + b[r] )   r<3
__global__ void wg_kernel(const float* __restrict__ summary, const float* __restrict__ W,
                          const float* __restrict__ b, float* __restrict__ wg) {
    __shared__ float red[512];
    int tid = threadIdx.x;
    for (int r = 0; r < RR; r++) {
        red[tid] = summary[tid] * W[(size_t)r * DD + tid];
        __syncthreads();
        #pragma unroll
        for (int o = 256; o > 0; o >>= 1) { if (tid < o) red[tid] += red[tid + o]; __syncthreads(); }
        if (tid == 0) wg[r] = 1.f / (1.f + expf(-(red[0] + b[r])));
        __syncthreads();
    }
}

// regs[r*256+k] += wg[r] * sum_d summary[d]*Wp[r*512*256 + d*256 + k]
__global__ void regsupd_kernel(const float* __restrict__ summary, const float* __restrict__ Wp,
                               const float* __restrict__ wg, float* __restrict__ regs) {
    int r = blockIdx.x;
    int k = threadIdx.x;
    const float* W = Wp + (size_t)r * DD * DRR;
    float acc = 0.f;
    for (int d = 0; d < DD; d++)
        acc += summary[d] * W[(size_t)d * DRR + k];
    regs[r * DRR + k] += wg[r] * acc;
}

__global__ void bankcopy_kernel(const float* __restrict__ regs, float* __restrict__ banks, int p) {
    int j = threadIdx.x;
    banks[p * RDR + j] = regs[j];
}

// residual[b,l,d] += mo[b,d]
__global__ void resmo_kernel(float* __restrict__ res, const float* __restrict__ mo) {
    size_t i = (size_t)blockIdx.x * blockDim.x + threadIdx.x;
    int d = (int)(i & 511);
    int b = (int)(i >> 20);   // 2048*512 = 1<<20
    res[i] += mo[(b << 9) + d];
}

// ---------------- GEMM: C[M,N] = act(A[M,K] @ B[K,N] + bias[N]) ----------------
// BM=BN=128, BK=8, 256 threads, 8x8 per thread. ACT: 0 none, 1 exact GELU.
template <int ACT>
__global__ void sgemm_kernel(const float* __restrict__ A, const float* __restrict__ B,
                             const float* __restrict__ bias, float* __restrict__ C,
                             int M, int N, int K) {
    __shared__ float As[8][128];
    __shared__ float Bs[8][128];
    const int bx = blockIdx.x;
    const int by = blockIdx.y;
    const int tid = threadIdx.x;
    const int tx = tid & 15;
    const int ty = tid >> 4;

    float acc[8][8];
    #pragma unroll
    for (int i = 0; i < 8; i++)
        #pragma unroll
        for (int j = 0; j < 8; j++) acc[i][j] = 0.f;

    const int a_row = tid >> 1;
    const int a_col = (tid & 1) * 4;
    const int b_row = tid >> 5;
    const int b_col = (tid & 31) * 4;

    const float* Ap = A + (size_t)(by * 128 + a_row) * K + a_col;
    const float* Bp = B + (size_t)b_row * N + bx * 128 + b_col;

    for (int k0 = 0; k0 < K; k0 += 8) {
        float4 av = *reinterpret_cast<const float4*>(Ap);
        float4 bv = *reinterpret_cast<const float4*>(Bp);
        As[a_col + 0][a_row] = av.x;
        As[a_col + 1][a_row] = av.y;
        As[a_col + 2][a_row] = av.z;
        As[a_col + 3][a_row] = av.w;
        *reinterpret_cast<float4*>(&Bs[b_row][b_col]) = bv;
        __syncthreads();
        #pragma unroll
        for (int k = 0; k < 8; k++) {
            float4 a0 = *reinterpret_cast<const float4*>(&As[k][ty * 8]);
            float4 a1 = *reinterpret_cast<const float4*>(&As[k][ty * 8 + 4]);
            float4 b0 = *reinterpret_cast<const float4*>(&Bs[k][tx * 8]);
            float4 b1 = *reinterpret_cast<const float4*>(&Bs[k][tx * 8 + 4]);
            float ar[8] = {a0.x, a0.y, a0.z, a0.w, a1.x, a1.y, a1.z, a1.w};
            float br[8] = {b0.x, b0.y, b0.z, b0.w, b1.x, b1.y, b1.z, b1.w};
            #pragma unroll
            for (int i = 0; i < 8; i++)
                #pragma unroll
                for (int j = 0; j < 8; j++)
                    acc[i][j] = fmaf(ar[i], br[j], acc[i][j]);
        }
        __syncthreads();
        Ap += 8;
        Bp += (size_t)8 * N;
    }

    const int crow0 = by * 128 + ty * 8;
    const int ccol0 = bx * 128 + tx * 8;
    #pragma unroll
    for (int i = 0; i < 8; i++) {
        float* Crow = C + (size_t)(crow0 + i) * N + ccol0;
        #pragma unroll
        for (int j = 0; j < 8; j++) {
            float v = acc[i][j] + bias[ccol0 + j];
            if (ACT == 1) v = 0.5f * v * (1.0f + erff(v * 0.70710678118654752f));
            Crow[j] = v;
        }
    }
}

// ---------------- host orchestration ----------------

extern "C" void kernel_launch(void* const* d_in, const int* in_sizes, int n_in,
                              void* d_out, int out_size) {
    const float* x        = (const float*)d_in[0];
    const float* reg_init = (const float*)d_in[1];
    const float* ffn_ln_s = (const float*)d_in[2];
    const float* ffn_ln_b = (const float*)d_in[3];
    const float* ffn_w1   = (const float*)d_in[4];
    const float* ffn_b1   = (const float*)d_in[5];
    const float* ffn_w2   = (const float*)d_in[6];
    const float* ffn_b2   = (const float*)d_in[7];
    const float* gate_w   = (const float*)d_in[8];
    const float* gate_b   = (const float*)d_in[9];
    const float* wproj_w  = (const float*)d_in[10];
    const float* wgate_w  = (const float*)d_in[11];
    const float* wgate_b  = (const float*)d_in[12];
    const float* s4_q     = (const float*)d_in[13];
    const float* s4_k     = (const float*)d_in[14];
    const float* s4_v     = (const float*)d_in[15];
    const float* s4_sum   = (const float*)d_in[16];
    const float* s4_ln_s  = (const float*)d_in[17];
    const float* s4_ln_b  = (const float*)d_in[18];
    const float* ms3_w    = (const float*)d_in[19];
    const float* ms3_b    = (const float*)d_in[20];
    const float* m4_q     = (const float*)d_in[21];
    const float* m4_k     = (const float*)d_in[22];
    const float* m4_v     = (const float*)d_in[23];
    const float* m4_out   = (const float*)d_in[24];
    const float* m4_ln_s  = (const float*)d_in[25];
    const float* m4_ln_b  = (const float*)d_in[26];
    const float* out_ln_s = (const float*)d_in[27];
    const float* out_ln_b = (const float*)d_in[28];

    float* S = nullptr;
    cudaGetSymbolAddress((void**)&S, g_scratch);

    float* res    = S + OFF_RES;
    float* xn     = S + OFF_XN;
    float* h      = S + OFF_H;
    float* delta  = S + OFF_DELTA;
    float* sc     = S + OFF_SC;
    float* part   = S + OFF_PART;
    float* q      = S + OFF_Q;
    float* kq     = S + OFF_KQ;
    float* wxm    = S + OFF_WXM;
    float* summ   = S + OFF_SUMM;
    float* regs   = S + OFF_REGS;      // gin = [regs | summary] contiguous
    float* sumry  = S + OFF_SUMRY;
    float* gate   = S + OFF_GATE;
    float* wg     = S + OFF_WG;
    float* banks  = S + OFF_BANKS;
    float* pw     = S + OFF_PW;
    float* wxb    = S + OFF_WXB;
    float* ms1    = S + OFF_MS1;
    float* mo     = S + OFF_MO;

    const int ELEM = NTOK * DD;                 // 4194304
    copy_kernel<<<ELEM / 256, 256>>>(x, res);
    passw_kernel<<<1, 32>>>(reg_init, ms3_w, ms3_b, pw);

    for (int p = 0; p < PP; p++) {
        // ---- S4 read (collapsed attention) ----
        qproj_kernel<<<2, 256>>>(banks, p * RDR, s4_q, q);
        matvec_kernel<<<512, 128>>>(s4_k, q, kq);
        ln_kernel<<<NTOK, 256>>>(res, xn, s4_ln_s, s4_ln_b, kq, sc);
        softmax_kernel<<<BB, 1024>>>(sc);
        wxpart_kernel<<<128, 512>>>(sc, xn, part);
        part_reduce_kernel<<<1, 512>>>(part, wxm, 128, 1.0f / BB);
        vecmat_kernel<<<2, 256>>>(wxm, s4_v, nullptr, nullptr, summ, DD, DD, 0);
        vecmat_kernel<<<3, 256>>>(summ, s4_sum, nullptr, reg_init, regs, DD, RDR, 0);

        for (int ph = 0; ph < PHH; ph++) {
            const int pp = p * PHH + ph;
            // FFN
            ln_kernel<<<NTOK, 256>>>(res, xn, ffn_ln_s + (size_t)ph * DD,
                                     ffn_ln_b + (size_t)ph * DD, nullptr, nullptr);
            {
                dim3 grid(FF / 128, NTOK / 128);
                sgemm_kernel<1><<<grid, 256>>>(xn, ffn_w1 + (size_t)ph * DD * FF,
                                               ffn_b1 + (size_t)ph * FF, h, NTOK, FF, DD);
            }
            {
                dim3 grid(DD / 128, NTOK / 128);
                sgemm_kernel<0><<<grid, 256>>>(h, ffn_w2 + (size_t)ph * FF * DD,
                                               ffn_b2 + (size_t)ph * DD, delta, NTOK, DD, FF);
            }
            // summary = mean over tokens of delta
            colsum_part_kernel<<<128, 512>>>(delta, part);
            part_reduce_kernel<<<1, 512>>>(part, sumry, 128, 1.0f / (float)NTOK);
            // gate = sigmoid([regs|summary] @ gate_w + gate_b)
            vecmat_kernel<<<2, 256>>>(regs, gate_w + (size_t)pp * (RDR + DD) * DD,
                                      gate_b + (size_t)pp * DD, nullptr, gate,
                                      RDR + DD, DD, 1);
            resupd_kernel<<<ELEM / 256, 256>>>(res, delta, gate, pw, p);
            // register update
            wg_kernel<<<1, 512>>>(sumry, wgate_w + (size_t)pp * RR * DD,
                                  wgate_b + (size_t)pp * RR, wg);
            regsupd_kernel<<<RR, DRR>>>(sumry, wproj_w + (size_t)pp * RR * DD * DRR, wg, regs);
        }
        bankcopy_kernel<<<1, RDR>>>(regs, banks, p);
    }

    // ---- MetaS4 ----
    qproj_kernel<<<2, 256>>>(banks, PP * RDR, m4_q, q);
    matvec_kernel<<<512, 128>>>(m4_k, q, kq);
    ln_kernel<<<NTOK, 256>>>(res, xn, m4_ln_s, m4_ln_b, kq, sc);
    softmax_kernel<<<BB, 1024>>>(sc);
    wxpart_kernel<<<128, 512>>>(sc, xn, part);
    part_reduce_kernel<<<BB, 512>>>(part, wxb, 32, 1.0f);
    for (int b = 0; b < BB; b++) {
        vecmat_kernel<<<2, 256>>>(wxb + (size_t)b * DD, m4_v, nullptr, nullptr,
                                  ms1 + (size_t)b * DD, DD, DD, 0);
        vecmat_kernel<<<2, 256>>>(ms1 + (size_t)b * DD, m4_out, nullptr, nullptr,
                                  mo + (size_t)b * DD, DD, DD, 0);
    }
    resmo_kernel<<<ELEM / 256, 256>>>(res, mo);

    // ---- final LayerNorm -> output ----
    ln_kernel<<<NTOK, 256>>>(res, (float*)d_out, out_ln_s, out_ln_b, nullptr, nullptr);
}

// round 3
// speedup vs baseline: 1.5316x; 1.5316x over previous
#include <cuda_runtime.h>
#include <cuda_bf16.h>
#include <math.h>
#include <stdint.h>

// ---------------- problem constants ----------------
#define BB 4
#define LL 2048
#define DD 512
#define DRR 256
#define RR 3
#define PP 5
#define PHH 3
#define FF 1536
#define NTOK (BB*LL)            // 8192
#define RDR (RR*DRR)            // 768

// ---------------- device scratch ----------------
__device__ __align__(256) float g_res[NTOK*DD];
__device__ __align__(256) float g_xn[NTOK*DD];
__device__ __align__(256) float g_delta[NTOK*DD];
__device__ __align__(256) float g_sc[NTOK];
__device__ __align__(256) float g_part[128*DD];
__device__ __align__(256) float g_q[DD];
__device__ __align__(256) float g_kq[DD];
__device__ __align__(256) float g_wxm[DD];
__device__ __align__(256) float g_summ[DD];
__device__ __align__(256) float g_regs[RDR + DD];   // gin = [regs | summary]
__device__ __align__(256) float g_gate[DD];
__device__ __align__(256) float g_wg[16];
__device__ __align__(256) float g_banks[PP*RDR];
__device__ __align__(256) float g_pw[16];
__device__ __align__(256) float g_wxb[BB*DD];
__device__ __align__(256) float g_ms1[BB*DD];
__device__ __align__(256) float g_mo[BB*DD];

__device__ __align__(256) __nv_bfloat16 g_xnh[NTOK*DD];
__device__ __align__(256) __nv_bfloat16 g_xnl[NTOK*DD];
__device__ __align__(256) __nv_bfloat16 g_hh[NTOK*FF];
__device__ __align__(256) __nv_bfloat16 g_hl[NTOK*FF];
__device__ __align__(256) __nv_bfloat16 g_w1th[PHH*FF*DD];
__device__ __align__(256) __nv_bfloat16 g_w1tl[PHH*FF*DD];
__device__ __align__(256) __nv_bfloat16 g_w2th[PHH*DD*FF];
__device__ __align__(256) __nv_bfloat16 g_w2tl[PHH*DD*FF];

// ---------------- PTX helpers (arch-agnostic: sm_80+) ----------------
__device__ __forceinline__ uint32_t smem_u32(const void* p) {
    return (uint32_t)__cvta_generic_to_shared(p);
}
__device__ __forceinline__ void cpasync16(uint32_t dst, const void* src) {
    asm volatile("cp.async.cg.shared.global [%0], [%1], 16;" :: "r"(dst), "l"(src) : "memory");
}
__device__ __forceinline__ void cp_commit() {
    asm volatile("cp.async.commit_group;" ::: "memory");
}
__device__ __forceinline__ void cp_wait1() {
    asm volatile("cp.async.wait_group 1;" ::: "memory");
}
__device__ __forceinline__ void ldsm4(uint32_t* r, uint32_t addr) {
    asm volatile("ldmatrix.sync.aligned.m8n8.x4.shared.b16 {%0,%1,%2,%3}, [%4];"
                 : "=r"(r[0]), "=r"(r[1]), "=r"(r[2]), "=r"(r[3]) : "r"(addr));
}
__device__ __forceinline__ void mma16816(float* c, const uint32_t* a, uint32_t b0, uint32_t b1) {
    asm volatile(
        "mma.sync.aligned.m16n8k16.row.col.f32.bf16.bf16.f32 "
        "{%0,%1,%2,%3}, {%4,%5,%6,%7}, {%8,%9}, {%0,%1,%2,%3};"
        : "+f"(c[0]), "+f"(c[1]), "+f"(c[2]), "+f"(c[3])
        : "r"(a[0]), "r"(a[1]), "r"(a[2]), "r"(a[3]), "r"(b0), "r"(b1));
}

// ---------------- split-bf16 GEMM via mma.sync ----------------
// C[M,N] = A[M,K] @ B^T   A=[M,K] rows (Ah+Al), B=[N,K] rows (Bh+Bl).
// Triple pass Ah*Bh + Ah*Bl + Al*Bh, fp32 register accumulators.
// OUTMODE 0: Cf = acc + bias. OUTMODE 1: v=gelu(acc+bias); Ch/Cl = bf16 hi/lo split.
// CTA tile 128x128, 256 thr (8 warps: 4m x 2n, warp tile 32x64), kchunk 32,
// 3-stage cp.async pipeline, XOR-swizzled K-major smem, ldmatrix.x4 operands.

#define STAGE_BYTES 16384           // A 8KB + B 8KB
#define NSTAGE 3

template <int OUTMODE>
__global__ void __launch_bounds__(256, 2)
mmagemm_kernel(const __nv_bfloat16* __restrict__ Ah, const __nv_bfloat16* __restrict__ Al,
               const __nv_bfloat16* __restrict__ Bh, const __nv_bfloat16* __restrict__ Bl,
               const float* __restrict__ bias,
               float* __restrict__ Cf, __nv_bfloat16* __restrict__ Ch,
               __nv_bfloat16* __restrict__ Cl,
               int M, int N, int K) {
    __shared__ __align__(128) unsigned char smem[NSTAGE * STAGE_BYTES];

    const int tid  = threadIdx.x;
    const int wid  = tid >> 5;
    const int lane = tid & 31;
    const int n0 = blockIdx.x * 128;
    const int m0 = blockIdx.y * 128;

    const int cpp = K >> 5;             // chunks per pass
    const int NIT = 3 * cpp;

    // this thread's two 16B segments of each tile (A and B identical pattern):
    // seg s (0..511): row = s>>2, c = s&3; swizzled column c^(row&3)
    const int sg0 = tid, sg1 = tid + 256;
    const int r0s = sg0 >> 2, c0s = sg0 & 3;
    const int r1s = sg1 >> 2, c1s = sg1 & 3;
    const uint32_t smem_base = smem_u32(smem);
    const uint32_t dA0 = (uint32_t)(((r0s << 2) + (c0s ^ (r0s & 3))) << 4);
    const uint32_t dA1 = (uint32_t)(((r1s << 2) + (c1s ^ (r1s & 3))) << 4);

    // prefetch chunk `it` into stage slot
    auto prefetch = [&](int it) {
        const int s  = it / cpp;
        const int k0 = (it % cpp) << 5;
        const __nv_bfloat16* Ap = (s == 2) ? Al : Ah;
        const __nv_bfloat16* Bp = (s == 1) ? Bl : Bh;
        const uint32_t st = smem_base + (uint32_t)(it % NSTAGE) * STAGE_BYTES;
        cpasync16(st + dA0,        Ap + (size_t)(m0 + r0s) * K + k0 + c0s * 8);
        cpasync16(st + dA1,        Ap + (size_t)(m0 + r1s) * K + k0 + c1s * 8);
        cpasync16(st + 8192 + dA0, Bp + (size_t)(n0 + r0s) * K + k0 + c0s * 8);
        cpasync16(st + 8192 + dA1, Bp + (size_t)(n0 + r1s) * K + k0 + c1s * 8);
        cp_commit();
    };

    float acc[2][8][4];
    #pragma unroll
    for (int i = 0; i < 2; i++)
        #pragma unroll
        for (int j = 0; j < 8; j++)
            #pragma unroll
            for (int t = 0; t < 4; t++) acc[i][j][t] = 0.f;

    const int wm = (wid & 3) * 32;      // warp m-offset in tile
    const int wn = (wid >> 2) * 64;     // warp n-offset in tile
    const int lrow = lane & 15;         // ldmatrix row-within-16
    const int lseg = lane >> 4;         // ldmatrix seg half

    prefetch(0);
    prefetch(1);

    #pragma unroll 1
    for (int it = 0; it < NIT; it++) {
        cp_wait1();
        __syncthreads();
        if (it + 2 < NIT) prefetch(it + 2);

        const uint32_t st = smem_base + (uint32_t)(it % NSTAGE) * STAGE_BYTES;
        #pragma unroll
        for (int kk = 0; kk < 2; kk++) {            // two k16 per chunk
            uint32_t af[2][4];
            #pragma unroll
            for (int i = 0; i < 2; i++) {
                int row = wm + i * 16 + lrow;
                int seg = kk * 2 + lseg;
                ldsm4(af[i], st + (uint32_t)(((row << 2) + (seg ^ (row & 3))) << 4));
            }
            uint32_t bf[4][4];
            #pragma unroll
            for (int g = 0; g < 4; g++) {
                int row = wn + g * 16 + lrow;
                int seg = kk * 2 + lseg;
                ldsm4(bf[g], st + 8192u + (uint32_t)(((row << 2) + (seg ^ (row & 3))) << 4));
            }
            #pragma unroll
            for (int i = 0; i < 2; i++)
                #pragma unroll
                for (int j = 0; j < 8; j++) {
                    int g = j >> 1, w = j & 1;
                    mma16816(acc[i][j], af[i], bf[g][w], bf[g][w + 2]);
                }
        }
    }

    // ---- epilogue: straight from register fragments ----
    const int l4 = lane >> 2;
    const int l2 = (lane & 3) * 2;
    #pragma unroll
    for (int i = 0; i < 2; i++) {
        #pragma unroll
        for (int j = 0; j < 8; j++) {
            const int col  = n0 + wn + j * 8 + l2;
            const int row0 = m0 + wm + i * 16 + l4;
            const float b0v = bias[col];
            const float b1v = bias[col + 1];
            float v00 = acc[i][j][0] + b0v, v01 = acc[i][j][1] + b1v;   // row0
            float v10 = acc[i][j][2] + b0v, v11 = acc[i][j][3] + b1v;   // row0+8
            if (OUTMODE == 0) {
                *(float2*)(Cf + (size_t)row0 * N + col)       = make_float2(v00, v01);
                *(float2*)(Cf + (size_t)(row0 + 8) * N + col) = make_float2(v10, v11);
            } else {
                #pragma unroll
                for (int t = 0; t < 1; t++) {}  // keep compiler happy
                float vv[4] = {v00, v01, v10, v11};
                unsigned short hh_[4], ll_[4];
                #pragma unroll
                for (int t = 0; t < 4; t++) {
                    float v = vv[t];
                    v = 0.5f * v * (1.0f + erff(v * 0.70710678118654752f));
                    __nv_bfloat16 hi = __float2bfloat16(v);
                    float fhi = __bfloat162float(hi);
                    __nv_bfloat16 lo = __float2bfloat16(v - fhi);
                    hh_[t] = __bfloat16_as_ushort(hi);
                    ll_[t] = __bfloat16_as_ushort(lo);
                }
                *(ushort2*)((unsigned short*)Ch + (size_t)row0 * N + col)       = make_ushort2(hh_[0], hh_[1]);
                *(ushort2*)((unsigned short*)Cl + (size_t)row0 * N + col)       = make_ushort2(ll_[0], ll_[1]);
                *(ushort2*)((unsigned short*)Ch + (size_t)(row0 + 8) * N + col) = make_ushort2(hh_[2], hh_[3]);
                *(ushort2*)((unsigned short*)Cl + (size_t)(row0 + 8) * N + col) = make_ushort2(ll_[2], ll_[3]);
            }
        }
    }
}

// ---------------- transpose + bf16 split: in[Rr,Cc] -> out[Cc,Rr] ----------------
__global__ void transpose_split_kernel(const float* __restrict__ in,
                                       __nv_bfloat16* __restrict__ oh,
                                       __nv_bfloat16* __restrict__ ol,
                                       int Rr, int Cc) {
    __shared__ float t[32][33];
    int r = blockIdx.y * 32 + threadIdx.y;
    int c = blockIdx.x * 32 + threadIdx.x;
    t[threadIdx.y][threadIdx.x] = in[(size_t)r * Cc + c];
    __syncthreads();
    int orow = blockIdx.x * 32 + threadIdx.y;   // out row = original col
    int ocol = blockIdx.y * 32 + threadIdx.x;   // out col = original row
    float v = t[threadIdx.x][threadIdx.y];
    __nv_bfloat16 hi = __float2bfloat16(v);
    float fhi = __bfloat162float(hi);
    __nv_bfloat16 lo = __float2bfloat16(v - fhi);
    oh[(size_t)orow * Rr + ocol] = hi;
    ol[(size_t)orow * Rr + ocol] = lo;
}

// ---------------- small kernels (round-1, proven) ----------------

__global__ void copy_kernel(const float* __restrict__ src, float* __restrict__ dst) {
    size_t i = (size_t)blockIdx.x * blockDim.x + threadIdx.x;
    dst[i] = src[i];
}

__global__ void passw_kernel(const float* __restrict__ reg_init,
                             const float* __restrict__ W,
                             const float* __restrict__ b,
                             float* __restrict__ pw) {
    int p = threadIdx.x;
    if (p >= PP) return;
    float acc = 0.f;
    for (int i = 0; i < PP * RDR; i++)
        acc += reg_init[i % RDR] * W[i * PP + p];
    pw[p] = 1.f / (1.f + expf(-(acc + b[p])));
}

__global__ void qproj_kernel(const float* __restrict__ bank, int n,
                             const float* __restrict__ Wq, float* __restrict__ q) {
    int d = blockIdx.x * blockDim.x + threadIdx.x;
    if (d >= DD) return;
    float acc = 0.f;
    for (int i = 0; i < n; i++)
        acc += bank[i] * Wq[(size_t)i * DD + d];
    q[d] = acc;
}

__global__ void matvec_kernel(const float* __restrict__ M,
                              const float* __restrict__ v,
                              float* __restrict__ out) {
    __shared__ float red[128];
    int r = blockIdx.x;
    int tid = threadIdx.x;
    float acc = 0.f;
    for (int j = tid; j < DD; j += 128)
        acc += M[(size_t)r * DD + j] * v[j];
    red[tid] = acc; __syncthreads();
    for (int o = 64; o > 0; o >>= 1) {
        if (tid < o) red[tid] += red[tid + o];
        __syncthreads();
    }
    if (tid == 0) out[r] = red[0];
}

__global__ void vecmat_kernel(const float* __restrict__ v, const float* __restrict__ M,
                              const float* __restrict__ bias, const float* __restrict__ init,
                              float* __restrict__ out, int nrow, int ncol, int act) {
    int j = blockIdx.x * blockDim.x + threadIdx.x;
    if (j >= ncol) return;
    float acc = 0.f;
    for (int d = 0; d < nrow; d++)
        acc += v[d] * M[(size_t)d * ncol + j];
    if (bias) acc += bias[j];
    if (init) acc += init[j];
    if (act == 1) acc = 1.f / (1.f + expf(-acc));
    out[j] = acc;
}

__global__ void ln_kernel(const float* __restrict__ in, float* __restrict__ out,
                          const float* __restrict__ gs, const float* __restrict__ gb,
                          const float* __restrict__ kq, float* __restrict__ score) {
    __shared__ float red[256];
    int t = blockIdx.x;
    int tid = threadIdx.x;
    const float* row = in + (size_t)t * DD;
    float x0 = row[tid];
    float x1 = row[tid + 256];
    red[tid] = x0 + x1; __syncthreads();
    #pragma unroll
    for (int o = 128; o > 0; o >>= 1) { if (tid < o) red[tid] += red[tid + o]; __syncthreads(); }
    float mean = red[0] * (1.0f / 512.0f);
    __syncthreads();
    float d0 = x0 - mean, d1 = x1 - mean;
    red[tid] = d0 * d0 + d1 * d1; __syncthreads();
    #pragma unroll
    for (int o = 128; o > 0; o >>= 1) { if (tid < o) red[tid] += red[tid + o]; __syncthreads(); }
    float rstd = rsqrtf(red[0] * (1.0f / 512.0f) + 1e-5f);
    __syncthreads();
    float y0 = d0 * rstd * gs[tid] + gb[tid];
    float y1 = d1 * rstd * gs[tid + 256] + gb[tid + 256];
    out[(size_t)t * DD + tid] = y0;
    out[(size_t)t * DD + tid + 256] = y1;
    if (kq) {
        red[tid] = y0 * kq[tid] + y1 * kq[tid + 256]; __syncthreads();
        #pragma unroll
        for (int o = 128; o > 0; o >>= 1) { if (tid < o) red[tid] += red[tid + o]; __syncthreads(); }
        if (tid == 0) score[t] = red[0] * 0.044194173824159216f;
    }
}

// LayerNorm emitting bf16 hi/lo split (for the FFN GEMM input)
__global__ void ln_bf16_kernel(const float* __restrict__ in,
                               __nv_bfloat16* __restrict__ oh, __nv_bfloat16* __restrict__ ol,
                               const float* __restrict__ gs, const float* __restrict__ gb) {
    __shared__ float red[256];
    int t = blockIdx.x;
    int tid = threadIdx.x;
    const float* row = in + (size_t)t * DD;
    float x0 = row[tid];
    float x1 = row[tid + 256];
    red[tid] = x0 + x1; __syncthreads();
    #pragma unroll
    for (int o = 128; o > 0; o >>= 1) { if (tid < o) red[tid] += red[tid + o]; __syncthreads(); }
    float mean = red[0] * (1.0f / 512.0f);
    __syncthreads();
    float d0 = x0 - mean, d1 = x1 - mean;
    red[tid] = d0 * d0 + d1 * d1; __syncthreads();
    #pragma unroll
    for (int o = 128; o > 0; o >>= 1) { if (tid < o) red[tid] += red[tid + o]; __syncthreads(); }
    float rstd = rsqrtf(red[0] * (1.0f / 512.0f) + 1e-5f);
    float y0 = d0 * rstd * gs[tid] + gb[tid];
    float y1 = d1 * rstd * gs[tid + 256] + gb[tid + 256];
    __nv_bfloat16 h0 = __float2bfloat16(y0);
    __nv_bfloat16 h1 = __float2bfloat16(y1);
    oh[(size_t)t * DD + tid]       = h0;
    oh[(size_t)t * DD + tid + 256] = h1;
    ol[(size_t)t * DD + tid]       = __float2bfloat16(y0 - __bfloat162float(h0));
    ol[(size_t)t * DD + tid + 256] = __float2bfloat16(y1 - __bfloat162float(h1));
}

__global__ void softmax_kernel(float* __restrict__ sc) {
    __shared__ float red[1024];
    int b = blockIdx.x;
    float* p = sc + (size_t)b * LL;
    int tid = threadIdx.x;
    float v0 = p[tid], v1 = p[tid + 1024];
    red[tid] = fmaxf(v0, v1); __syncthreads();
    #pragma unroll
    for (int o = 512; o > 0; o >>= 1) { if (tid < o) red[tid] = fmaxf(red[tid], red[tid + o]); __syncthreads(); }
    float mx = red[0];
    __syncthreads();
    float e0 = expf(v0 - mx), e1 = expf(v1 - mx);
    red[tid] = e0 + e1; __syncthreads();
    #pragma unroll
    for (int o = 512; o > 0; o >>= 1) { if (tid < o) red[tid] += red[tid + o]; __syncthreads(); }
    float inv = 1.f / red[0];
    p[tid] = e0 * inv;
    p[tid + 1024] = e1 * inv;
}

__global__ void wxpart_kernel(const float* __restrict__ a, const float* __restrict__ xn,
                              float* __restrict__ part) {
    int d = threadIdx.x;
    int blk = blockIdx.x;
    int row0 = blk * 64;
    float acc = 0.f;
    for (int r = row0; r < row0 + 64; r++)
        acc += a[r] * xn[(size_t)r * DD + d];
    part[(size_t)blk * DD + d] = acc;
}

__global__ void colsum_part_kernel(const float* __restrict__ delta, float* __restrict__ part) {
    int d = threadIdx.x;
    int c = blockIdx.x;
    float acc = 0.f;
    for (int r = c * 64; r < (c + 1) * 64; r++)
        acc += delta[(size_t)r * DD + d];
    part[(size_t)c * DD + d] = acc;
}

__global__ void part_reduce_kernel(const float* __restrict__ part, float* __restrict__ out,
                                   int nchunk, float scale) {
    int d = threadIdx.x;
    int g = blockIdx.x;
    const float* p = part + (size_t)g * nchunk * DD;
    float acc = 0.f;
    for (int c = 0; c < nchunk; c++)
        acc += p[(size_t)c * DD + d];
    out[(size_t)g * DD + d] = acc * scale;
}

__global__ void resupd_kernel(float* __restrict__ res, const float* __restrict__ delta,
                              const float* __restrict__ gate, const float* __restrict__ pw, int p) {
    size_t i = (size_t)blockIdx.x * blockDim.x + threadIdx.x;
    res[i] += pw[p] * gate[i & 511] * delta[i];
}

__global__ void wg_kernel(const float* __restrict__ summary, const float* __restrict__ W,
                          const float* __restrict__ b, float* __restrict__ wg) {
    __shared__ float red[512];
    int tid = threadIdx.x;
    for (int r = 0; r < RR; r++) {
        red[tid] = summary[tid] * W[(size_t)r * DD + tid];
        __syncthreads();
        #pragma unroll
        for (int o = 256; o > 0; o >>= 1) { if (tid < o) red[tid] += red[tid + o]; __syncthreads(); }
        if (tid == 0) wg[r] = 1.f / (1.f + expf(-(red[0] + b[r])));
        __syncthreads();
    }
}

__global__ void regsupd_kernel(const float* __restrict__ summary, const float* __restrict__ Wp,
                               const float* __restrict__ wg, float* __restrict__ regs) {
    int r = blockIdx.x;
    int k = threadIdx.x;
    const float* W = Wp + (size_t)r * DD * DRR;
    float acc = 0.f;
    for (int d = 0; d < DD; d++)
        acc += summary[d] * W[(size_t)d * DRR + k];
    regs[r * DRR + k] += wg[r] * acc;
}

__global__ void bankcopy_kernel(const float* __restrict__ regs, float* __restrict__ banks, int p) {
    int j = threadIdx.x;
    banks[p * RDR + j] = regs[j];
}

__global__ void resmo_kernel(float* __restrict__ res, const float* __restrict__ mo) {
    size_t i = (size_t)blockIdx.x * blockDim.x + threadIdx.x;
    int d = (int)(i & 511);
    int b = (int)(i >> 20);
    res[i] += mo[(b << 9) + d];
}

// ---------------- host orchestration ----------------

extern "C" void kernel_launch(void* const* d_in, const int* in_sizes, int n_in,
                              void* d_out, int out_size) {
    const float* x        = (const float*)d_in[0];
    const float* reg_init = (const float*)d_in[1];
    const float* ffn_ln_s = (const float*)d_in[2];
    const float* ffn_ln_b = (const float*)d_in[3];
    const float* ffn_w1   = (const float*)d_in[4];
    const float* ffn_b1   = (const float*)d_in[5];
    const float* ffn_w2   = (const float*)d_in[6];
    const float* ffn_b2   = (const float*)d_in[7];
    const float* gate_w   = (const float*)d_in[8];
    const float* gate_b   = (const float*)d_in[9];
    const float* wproj_w  = (const float*)d_in[10];
    const float* wgate_w  = (const float*)d_in[11];
    const float* wgate_b  = (const float*)d_in[12];
    const float* s4_q     = (const float*)d_in[13];
    const float* s4_k     = (const float*)d_in[14];
    const float* s4_v     = (const float*)d_in[15];
    const float* s4_sum   = (const float*)d_in[16];
    const float* s4_ln_s  = (const float*)d_in[17];
    const float* s4_ln_b  = (const float*)d_in[18];
    const float* ms3_w    = (const float*)d_in[19];
    const float* ms3_b    = (const float*)d_in[20];
    const float* m4_q     = (const float*)d_in[21];
    const float* m4_k     = (const float*)d_in[22];
    const float* m4_v     = (const float*)d_in[23];
    const float* m4_out   = (const float*)d_in[24];
    const float* m4_ln_s  = (const float*)d_in[25];
    const float* m4_ln_b  = (const float*)d_in[26];
    const float* out_ln_s = (const float*)d_in[27];
    const float* out_ln_b = (const float*)d_in[28];

    float *res, *xn, *delta, *sc, *part, *q, *kq, *wxm, *summ, *regs, *gate, *wg;
    float *banks, *pw, *wxb, *ms1, *mo;
    __nv_bfloat16 *xnh, *xnl, *hh, *hl, *w1th, *w1tl, *w2th, *w2tl;
    cudaGetSymbolAddress((void**)&res,   g_res);
    cudaGetSymbolAddress((void**)&xn,    g_xn);
    cudaGetSymbolAddress((void**)&delta, g_delta);
    cudaGetSymbolAddress((void**)&sc,    g_sc);
    cudaGetSymbolAddress((void**)&part,  g_part);
    cudaGetSymbolAddress((void**)&q,     g_q);
    cudaGetSymbolAddress((void**)&kq,    g_kq);
    cudaGetSymbolAddress((void**)&wxm,   g_wxm);
    cudaGetSymbolAddress((void**)&summ,  g_summ);
    cudaGetSymbolAddress((void**)&regs,  g_regs);
    cudaGetSymbolAddress((void**)&gate,  g_gate);
    cudaGetSymbolAddress((void**)&wg,    g_wg);
    cudaGetSymbolAddress((void**)&banks, g_banks);
    cudaGetSymbolAddress((void**)&pw,    g_pw);
    cudaGetSymbolAddress((void**)&wxb,   g_wxb);
    cudaGetSymbolAddress((void**)&ms1,   g_ms1);
    cudaGetSymbolAddress((void**)&mo,    g_mo);
    cudaGetSymbolAddress((void**)&xnh,   g_xnh);
    cudaGetSymbolAddress((void**)&xnl,   g_xnl);
    cudaGetSymbolAddress((void**)&hh,    g_hh);
    cudaGetSymbolAddress((void**)&hl,    g_hl);
    cudaGetSymbolAddress((void**)&w1th,  g_w1th);
    cudaGetSymbolAddress((void**)&w1tl,  g_w1tl);
    cudaGetSymbolAddress((void**)&w2th,  g_w2th);
    cudaGetSymbolAddress((void**)&w2tl,  g_w2tl);

    const int ELEM = NTOK * DD;

    // weight transpose + split (per replay; cheap and deterministic)
    for (int ph = 0; ph < PHH; ph++) {
        dim3 blk(32, 32);
        dim3 g1(FF / 32, DD / 32);   // w1 [D,F] -> [F,D]
        transpose_split_kernel<<<g1, blk>>>(ffn_w1 + (size_t)ph * DD * FF,
                                            w1th + (size_t)ph * FF * DD,
                                            w1tl + (size_t)ph * FF * DD, DD, FF);
        dim3 g2(DD / 32, FF / 32);   // w2 [F,D] -> [D,F]
        transpose_split_kernel<<<g2, blk>>>(ffn_w2 + (size_t)ph * FF * DD,
                                            w2th + (size_t)ph * DD * FF,
                                            w2tl + (size_t)ph * DD * FF, FF, DD);
    }

    copy_kernel<<<ELEM / 256, 256>>>(x, res);
    passw_kernel<<<1, 32>>>(reg_init, ms3_w, ms3_b, pw);

    for (int p = 0; p < PP; p++) {
        // ---- S4 read (collapsed attention) ----
        qproj_kernel<<<2, 256>>>(banks, p * RDR, s4_q, q);
        matvec_kernel<<<512, 128>>>(s4_k, q, kq);
        ln_kernel<<<NTOK, 256>>>(res, xn, s4_ln_s, s4_ln_b, kq, sc);
        softmax_kernel<<<BB, 1024>>>(sc);
        wxpart_kernel<<<128, 512>>>(sc, xn, part);
        part_reduce_kernel<<<1, 512>>>(part, wxm, 128, 1.0f / BB);
        vecmat_kernel<<<2, 256>>>(wxm, s4_v, nullptr, nullptr, summ, DD, DD, 0);
        vecmat_kernel<<<3, 256>>>(summ, s4_sum, nullptr, reg_init, regs, DD, RDR, 0);

        for (int ph = 0; ph < PHH; ph++) {
            const int pp = p * PHH + ph;
            // FFN: LN -> split-bf16 GEMM (gelu, split out) -> split-bf16 GEMM (fp32 out)
            ln_bf16_kernel<<<NTOK, 256>>>(res, xnh, xnl,
                                          ffn_ln_s + (size_t)ph * DD,
                                          ffn_ln_b + (size_t)ph * DD);
            {
                dim3 grid(FF / 128, NTOK / 128);
                mmagemm_kernel<1><<<grid, 256>>>(xnh, xnl,
                                                 w1th + (size_t)ph * FF * DD,
                                                 w1tl + (size_t)ph * FF * DD,
                                                 ffn_b1 + (size_t)ph * FF,
                                                 nullptr, hh, hl, NTOK, FF, DD);
            }
            {
                dim3 grid(DD / 128, NTOK / 128);
                mmagemm_kernel<0><<<grid, 256>>>(hh, hl,
                                                 w2th + (size_t)ph * DD * FF,
                                                 w2tl + (size_t)ph * DD * FF,
                                                 ffn_b2 + (size_t)ph * DD,
                                                 delta, nullptr, nullptr, NTOK, DD, FF);
            }
            // summary = mean over tokens of delta
            colsum_part_kernel<<<128, 512>>>(delta, part);
            part_reduce_kernel<<<1, 512>>>(part, regs + RDR, 128, 1.0f / (float)NTOK);
            // gate = sigmoid([regs|summary] @ gate_w + gate_b)
            vecmat_kernel<<<2, 256>>>(regs, gate_w + (size_t)pp * (RDR + DD) * DD,
                                      gate_b + (size_t)pp * DD, nullptr, gate,
                                      RDR + DD, DD, 1);
            resupd_kernel<<<ELEM / 256, 256>>>(res, delta, gate, pw, p);
            // register update
            wg_kernel<<<1, 512>>>(regs + RDR, wgate_w + (size_t)pp * RR * DD,
                                  wgate_b + (size_t)pp * RR, wg);
            regsupd_kernel<<<RR, DRR>>>(regs + RDR, wproj_w + (size_t)pp * RR * DD * DRR,
                                        wg, regs);
        }
        bankcopy_kernel<<<1, RDR>>>(regs, banks, p);
    }

    // ---- MetaS4 ----
    qproj_kernel<<<2, 256>>>(banks, PP * RDR, m4_q, q);
    matvec_kernel<<<512, 128>>>(m4_k, q, kq);
    ln_kernel<<<NTOK, 256>>>(res, xn, m4_ln_s, m4_ln_b, kq, sc);
    softmax_kernel<<<BB, 1024>>>(sc);
    wxpart_kernel<<<128, 512>>>(sc, xn, part);
    part_reduce_kernel<<<BB, 512>>>(part, wxb, 32, 1.0f);
    for (int b = 0; b < BB; b++) {
        vecmat_kernel<<<2, 256>>>(wxb + (size_t)b * DD, m4_v, nullptr, nullptr,
                                  ms1 + (size_t)b * DD, DD, DD, 0);
        vecmat_kernel<<<2, 256>>>(ms1 + (size_t)b * DD, m4_out, nullptr, nullptr,
                                  mo + (size_t)b * DD, DD, DD, 0);
    }
    resmo_kernel<<<ELEM / 256, 256>>>(res, mo);

    // ---- final LayerNorm -> output ----
    ln_kernel<<<NTOK, 256>>>(res, (float*)d_out, out_ln_s, out_ln_b, nullptr, nullptr);
}

// round 4
// speedup vs baseline: 1.8407x; 1.2018x over previous
#include <cuda_runtime.h>
#include <cuda_fp16.h>
#include <cuda_bf16.h>
#include <math.h>
#include <stdint.h>

// ---------------- problem constants ----------------
#define BB 4
#define LL 2048
#define DD 512
#define DRR 256
#define RR 3
#define PP 5
#define PHH 3
#define FF 1536
#define NTOK (BB*LL)            // 8192
#define RDR (RR*DRR)            // 768

// ---------------- device scratch ----------------
__device__ __align__(256) float g_res[NTOK*DD];
__device__ __align__(256) float g_xn[NTOK*DD];
__device__ __align__(256) float g_delta[NTOK*DD];
__device__ __align__(256) float g_sc[NTOK];
__device__ __align__(256) float g_part[128*DD];
__device__ __align__(256) float g_q[DD];
__device__ __align__(256) float g_kq[DD];
__device__ __align__(256) float g_wxm[DD];
__device__ __align__(256) float g_summ[DD];
__device__ __align__(256) float g_regs[RDR + DD];   // gin = [regs | summary]
__device__ __align__(256) float g_gate[DD];
__device__ __align__(256) float g_wg[16];
__device__ __align__(256) float g_banks[PP*RDR];
__device__ __align__(256) float g_pw[16];
__device__ __align__(256) float g_wxb[BB*DD];
__device__ __align__(256) float g_ms1[BB*DD];
__device__ __align__(256) float g_mo[BB*DD];

__device__ __align__(256) __half g_xnh[NTOK*DD];
__device__ __align__(256) __half g_xnl[NTOK*DD];
__device__ __align__(256) __half g_hh[NTOK*FF];
__device__ __align__(256) __half g_hl[NTOK*FF];
__device__ __align__(256) __half g_w1th[PHH*FF*DD];
__device__ __align__(256) __half g_w2th[PHH*DD*FF];

// ---------------- PTX helpers (arch-agnostic: sm_80+) ----------------
__device__ __forceinline__ uint32_t smem_u32(const void* p) {
    return (uint32_t)__cvta_generic_to_shared(p);
}
__device__ __forceinline__ void cpasync16(uint32_t dst, const void* src) {
    asm volatile("cp.async.cg.shared.global [%0], [%1], 16;" :: "r"(dst), "l"(src) : "memory");
}
__device__ __forceinline__ void cp_commit() {
    asm volatile("cp.async.commit_group;" ::: "memory");
}
__device__ __forceinline__ void cp_wait1() {
    asm volatile("cp.async.wait_group 1;" ::: "memory");
}
__device__ __forceinline__ void ldsm4(uint32_t* r, uint32_t addr) {
    asm volatile("ldmatrix.sync.aligned.m8n8.x4.shared.b16 {%0,%1,%2,%3}, [%4];"
                 : "=r"(r[0]), "=r"(r[1]), "=r"(r[2]), "=r"(r[3]) : "r"(addr));
}
__device__ __forceinline__ void mma16816(float* c, const uint32_t* a, uint32_t b0, uint32_t b1) {
    asm volatile(
        "mma.sync.aligned.m16n8k16.row.col.f32.f16.f16.f32 "
        "{%0,%1,%2,%3}, {%4,%5,%6,%7}, {%8,%9}, {%0,%1,%2,%3};"
        : "+f"(c[0]), "+f"(c[1]), "+f"(c[2]), "+f"(c[3])
        : "r"(a[0]), "r"(a[1]), "r"(a[2]), "r"(a[3]), "r"(b0), "r"(b1));
}

// ---------------- split-fp16 GEMM via mma.sync (single K-sweep) ----------------
// C[M,N] = A[M,K] @ B^T   A = Ah + Al (exact fp16 split), B rows [N,K] as Bh=fp16(B).
// C = (Ah+Al)·Bh = A·Bh : only error is A·(B-Bh) ~ 2^-11 relative of B.
// OUTMODE 0: Cf = acc + bias. OUTMODE 1: v=gelu(acc+bias); Ch/Cl = fp16 hi/lo split.
// CTA tile 128x128, 256 thr (8 warps: 4m x 2n, warp tile 32x64), kchunk 32,
// 2-stage cp.async pipeline, XOR-swizzled K-major smem, ldmatrix.x4 operands.

#define STAGE_BYTES 24576           // Ah 8KB + Al 8KB + Bh 8KB
#define NSTAGE 2

template <int OUTMODE>
__global__ void __launch_bounds__(256, 2)
mmagemm_kernel(const __half* __restrict__ Ah, const __half* __restrict__ Al,
               const __half* __restrict__ Bh,
               const float* __restrict__ bias,
               float* __restrict__ Cf, __half* __restrict__ Ch, __half* __restrict__ Cl,
               int M, int N, int K) {
    __shared__ __align__(128) unsigned char smem[NSTAGE * STAGE_BYTES];   // 48KB

    const int tid  = threadIdx.x;
    const int wid  = tid >> 5;
    const int lane = tid & 31;
    const int n0 = blockIdx.x * 128;
    const int m0 = blockIdx.y * 128;

    const int NIT = K >> 5;             // k32 chunks, single sweep

    // this thread's two 16B segments of each 8KB tile:
    // seg s (0..511): row = s>>2, c = s&3; swizzled column c^(row&3)
    const int sg0 = tid, sg1 = tid + 256;
    const int r0s = sg0 >> 2, c0s = sg0 & 3;
    const int r1s = sg1 >> 2, c1s = sg1 & 3;
    const uint32_t smem_base = smem_u32(smem);
    const uint32_t dA0 = (uint32_t)(((r0s << 2) + (c0s ^ (r0s & 3))) << 4);
    const uint32_t dA1 = (uint32_t)(((r1s << 2) + (c1s ^ (r1s & 3))) << 4);

    auto prefetch = [&](int it) {
        const int k0 = it << 5;
        const uint32_t st = smem_base + (uint32_t)(it & 1) * STAGE_BYTES;
        cpasync16(st + dA0,          Ah + (size_t)(m0 + r0s) * K + k0 + c0s * 8);
        cpasync16(st + dA1,          Ah + (size_t)(m0 + r1s) * K + k0 + c1s * 8);
        cpasync16(st + 8192 + dA0,   Al + (size_t)(m0 + r0s) * K + k0 + c0s * 8);
        cpasync16(st + 8192 + dA1,   Al + (size_t)(m0 + r1s) * K + k0 + c1s * 8);
        cpasync16(st + 16384 + dA0,  Bh + (size_t)(n0 + r0s) * K + k0 + c0s * 8);
        cpasync16(st + 16384 + dA1,  Bh + (size_t)(n0 + r1s) * K + k0 + c1s * 8);
        cp_commit();
    };

    float acc[2][8][4];
    #pragma unroll
    for (int i = 0; i < 2; i++)
        #pragma unroll
        for (int j = 0; j < 8; j++)
            #pragma unroll
            for (int t = 0; t < 4; t++) acc[i][j][t] = 0.f;

    const int wm = (wid & 3) * 32;      // warp m-offset in tile
    const int wn = (wid >> 2) * 64;     // warp n-offset in tile
    const int lrow = lane & 15;
    const int lseg = lane >> 4;

    prefetch(0);
    prefetch(1);

    #pragma unroll 1
    for (int it = 0; it < NIT; it++) {
        cp_wait1();
        __syncthreads();

        const uint32_t st = smem_base + (uint32_t)(it & 1) * STAGE_BYTES;
        #pragma unroll
        for (int kk = 0; kk < 2; kk++) {            // two k16 per chunk
            uint32_t ahf[2][4], alf[2][4];
            #pragma unroll
            for (int i = 0; i < 2; i++) {
                int row = wm + i * 16 + lrow;
                int seg = kk * 2 + lseg;
                uint32_t off = (uint32_t)(((row << 2) + (seg ^ (row & 3))) << 4);
                ldsm4(ahf[i], st + off);
                ldsm4(alf[i], st + 8192u + off);
            }
            uint32_t bf[4][4];
            #pragma unroll
            for (int g = 0; g < 4; g++) {
                int row = wn + g * 16 + lrow;
                int seg = kk * 2 + lseg;
                ldsm4(bf[g], st + 16384u + (uint32_t)(((row << 2) + (seg ^ (row & 3))) << 4));
            }
            #pragma unroll
            for (int i = 0; i < 2; i++)
                #pragma unroll
                for (int j = 0; j < 8; j++) {
                    int g = j >> 1, w = j & 1;
                    mma16816(acc[i][j], ahf[i], bf[g][w], bf[g][w + 2]);
                }
            #pragma unroll
            for (int i = 0; i < 2; i++)
                #pragma unroll
                for (int j = 0; j < 8; j++) {
                    int g = j >> 1, w = j & 1;
                    mma16816(acc[i][j], alf[i], bf[g][w], bf[g][w + 2]);
                }
        }
        __syncthreads();
        if (it + 2 < NIT) prefetch(it + 2);
    }

    // ---- epilogue: straight from register fragments ----
    const int l4 = lane >> 2;
    const int l2 = (lane & 3) * 2;
    #pragma unroll
    for (int i = 0; i < 2; i++) {
        #pragma unroll
        for (int j = 0; j < 8; j++) {
            const int col  = n0 + wn + j * 8 + l2;
            const int row0 = m0 + wm + i * 16 + l4;
            const float b0v = bias[col];
            const float b1v = bias[col + 1];
            float v00 = acc[i][j][0] + b0v, v01 = acc[i][j][1] + b1v;   // row0
            float v10 = acc[i][j][2] + b0v, v11 = acc[i][j][3] + b1v;   // row0+8
            if (OUTMODE == 0) {
                *(float2*)(Cf + (size_t)row0 * N + col)       = make_float2(v00, v01);
                *(float2*)(Cf + (size_t)(row0 + 8) * N + col) = make_float2(v10, v11);
            } else {
                float vv[4] = {v00, v01, v10, v11};
                unsigned short hh_[4], ll_[4];
                #pragma unroll
                for (int t = 0; t < 4; t++) {
                    float v = vv[t];
                    v = 0.5f * v * (1.0f + erff(v * 0.70710678118654752f));
                    __half hi = __float2half_rn(v);
                    __half lo = __float2half_rn(v - __half2float(hi));
                    hh_[t] = __half_as_ushort(hi);
                    ll_[t] = __half_as_ushort(lo);
                }
                *(ushort2*)((unsigned short*)Ch + (size_t)row0 * N + col)       = make_ushort2(hh_[0], hh_[1]);
                *(ushort2*)((unsigned short*)Cl + (size_t)row0 * N + col)       = make_ushort2(ll_[0], ll_[1]);
                *(ushort2*)((unsigned short*)Ch + (size_t)(row0 + 8) * N + col) = make_ushort2(hh_[2], hh_[3]);
                *(ushort2*)((unsigned short*)Cl + (size_t)(row0 + 8) * N + col) = make_ushort2(ll_[2], ll_[3]);
            }
        }
    }
}

// ---------------- transpose + fp16: in[Rr,Cc] -> out[Cc,Rr] (hi only) ----------------
__global__ void transpose_half_kernel(const float* __restrict__ in,
                                      __half* __restrict__ oh,
                                      int Rr, int Cc) {
    __shared__ float t[32][33];
    int r = blockIdx.y * 32 + threadIdx.y;
    int c = blockIdx.x * 32 + threadIdx.x;
    t[threadIdx.y][threadIdx.x] = in[(size_t)r * Cc + c];
    __syncthreads();
    int orow = blockIdx.x * 32 + threadIdx.y;
    int ocol = blockIdx.y * 32 + threadIdx.x;
    oh[(size_t)orow * Rr + ocol] = __float2half_rn(t[threadIdx.x][threadIdx.y]);
}

// ---------------- small kernels (proven) ----------------

__global__ void copy_kernel(const float* __restrict__ src, float* __restrict__ dst) {
    size_t i = (size_t)blockIdx.x * blockDim.x + threadIdx.x;
    dst[i] = src[i];
}

__global__ void passw_kernel(const float* __restrict__ reg_init,
                             const float* __restrict__ W,
                             const float* __restrict__ b,
                             float* __restrict__ pw) {
    int p = threadIdx.x;
    if (p >= PP) return;
    float acc = 0.f;
    for (int i = 0; i < PP * RDR; i++)
        acc += reg_init[i % RDR] * W[i * PP + p];
    pw[p] = 1.f / (1.f + expf(-(acc + b[p])));
}

__global__ void qproj_kernel(const float* __restrict__ bank, int n,
                             const float* __restrict__ Wq, float* __restrict__ q) {
    int d = blockIdx.x * blockDim.x + threadIdx.x;
    if (d >= DD) return;
    float acc = 0.f;
    for (int i = 0; i < n; i++)
        acc += bank[i] * Wq[(size_t)i * DD + d];
    q[d] = acc;
}

__global__ void matvec_kernel(const float* __restrict__ M,
                              const float* __restrict__ v,
                              float* __restrict__ out) {
    __shared__ float red[128];
    int r = blockIdx.x;
    int tid = threadIdx.x;
    float acc = 0.f;
    for (int j = tid; j < DD; j += 128)
        acc += M[(size_t)r * DD + j] * v[j];
    red[tid] = acc; __syncthreads();
    for (int o = 64; o > 0; o >>= 1) {
        if (tid < o) red[tid] += red[tid + o];
        __syncthreads();
    }
    if (tid == 0) out[r] = red[0];
}

__global__ void vecmat_kernel(const float* __restrict__ v, const float* __restrict__ M,
                              const float* __restrict__ bias, const float* __restrict__ init,
                              float* __restrict__ out, int nrow, int ncol, int act) {
    int j = blockIdx.x * blockDim.x + threadIdx.x;
    if (j >= ncol) return;
    float acc = 0.f;
    for (int d = 0; d < nrow; d++)
        acc += v[d] * M[(size_t)d * ncol + j];
    if (bias) acc += bias[j];
    if (init) acc += init[j];
    if (act == 1) acc = 1.f / (1.f + expf(-acc));
    out[j] = acc;
}

__global__ void ln_kernel(const float* __restrict__ in, float* __restrict__ out,
                          const float* __restrict__ gs, const float* __restrict__ gb,
                          const float* __restrict__ kq, float* __restrict__ score) {
    __shared__ float red[256];
    int t = blockIdx.x;
    int tid = threadIdx.x;
    const float* row = in + (size_t)t * DD;
    float x0 = row[tid];
    float x1 = row[tid + 256];
    red[tid] = x0 + x1; __syncthreads();
    #pragma unroll
    for (int o = 128; o > 0; o >>= 1) { if (tid < o) red[tid] += red[tid + o]; __syncthreads(); }
    float mean = red[0] * (1.0f / 512.0f);
    __syncthreads();
    float d0 = x0 - mean, d1 = x1 - mean;
    red[tid] = d0 * d0 + d1 * d1; __syncthreads();
    #pragma unroll
    for (int o = 128; o > 0; o >>= 1) { if (tid < o) red[tid] += red[tid + o]; __syncthreads(); }
    float rstd = rsqrtf(red[0] * (1.0f / 512.0f) + 1e-5f);
    __syncthreads();
    float y0 = d0 * rstd * gs[tid] + gb[tid];
    float y1 = d1 * rstd * gs[tid + 256] + gb[tid + 256];
    out[(size_t)t * DD + tid] = y0;
    out[(size_t)t * DD + tid + 256] = y1;
    if (kq) {
        red[tid] = y0 * kq[tid] + y1 * kq[tid + 256]; __syncthreads();
        #pragma unroll
        for (int o = 128; o > 0; o >>= 1) { if (tid < o) red[tid] += red[tid + o]; __syncthreads(); }
        if (tid == 0) score[t] = red[0] * 0.044194173824159216f;
    }
}

// LayerNorm emitting fp16 hi/lo split (for the FFN GEMM input)
__global__ void ln_fp16_kernel(const float* __restrict__ in,
                               __half* __restrict__ oh, __half* __restrict__ ol,
                               const float* __restrict__ gs, const float* __restrict__ gb) {
    __shared__ float red[256];
    int t = blockIdx.x;
    int tid = threadIdx.x;
    const float* row = in + (size_t)t * DD;
    float x0 = row[tid];
    float x1 = row[tid + 256];
    red[tid] = x0 + x1; __syncthreads();
    #pragma unroll
    for (int o = 128; o > 0; o >>= 1) { if (tid < o) red[tid] += red[tid + o]; __syncthreads(); }
    float mean = red[0] * (1.0f / 512.0f);
    __syncthreads();
    float d0 = x0 - mean, d1 = x1 - mean;
    red[tid] = d0 * d0 + d1 * d1; __syncthreads();
    #pragma unroll
    for (int o = 128; o > 0; o >>= 1) { if (tid < o) red[tid] += red[tid + o]; __syncthreads(); }
    float rstd = rsqrtf(red[0] * (1.0f / 512.0f) + 1e-5f);
    float y0 = d0 * rstd * gs[tid] + gb[tid];
    float y1 = d1 * rstd * gs[tid + 256] + gb[tid + 256];
    __half h0 = __float2half_rn(y0);
    __half h1 = __float2half_rn(y1);
    oh[(size_t)t * DD + tid]       = h0;
    oh[(size_t)t * DD + tid + 256] = h1;
    ol[(size_t)t * DD + tid]       = __float2half_rn(y0 - __half2float(h0));
    ol[(size_t)t * DD + tid + 256] = __float2half_rn(y1 - __half2float(h1));
}

__global__ void softmax_kernel(float* __restrict__ sc) {
    __shared__ float red[1024];
    int b = blockIdx.x;
    float* p = sc + (size_t)b * LL;
    int tid = threadIdx.x;
    float v0 = p[tid], v1 = p[tid + 1024];
    red[tid] = fmaxf(v0, v1); __syncthreads();
    #pragma unroll
    for (int o = 512; o > 0; o >>= 1) { if (tid < o) red[tid] = fmaxf(red[tid], red[tid + o]); __syncthreads(); }
    float mx = red[0];
    __syncthreads();
    float e0 = expf(v0 - mx), e1 = expf(v1 - mx);
    red[tid] = e0 + e1; __syncthreads();
    #pragma unroll
    for (int o = 512; o > 0; o >>= 1) { if (tid < o) red[tid] += red[tid + o]; __syncthreads(); }
    float inv = 1.f / red[0];
    p[tid] = e0 * inv;
    p[tid + 1024] = e1 * inv;
}

__global__ void wxpart_kernel(const float* __restrict__ a, const float* __restrict__ xn,
                              float* __restrict__ part) {
    int d = threadIdx.x;
    int blk = blockIdx.x;
    int row0 = blk * 64;
    float acc = 0.f;
    for (int r = row0; r < row0 + 64; r++)
        acc += a[r] * xn[(size_t)r * DD + d];
    part[(size_t)blk * DD + d] = acc;
}

__global__ void colsum_part_kernel(const float* __restrict__ delta, float* __restrict__ part) {
    int d = threadIdx.x;
    int c = blockIdx.x;
    float acc = 0.f;
    for (int r = c * 64; r < (c + 1) * 64; r++)
        acc += delta[(size_t)r * DD + d];
    part[(size_t)c * DD + d] = acc;
}

__global__ void part_reduce_kernel(const float* __restrict__ part, float* __restrict__ out,
                                   int nchunk, float scale) {
    int d = threadIdx.x;
    int g = blockIdx.x;
    const float* p = part + (size_t)g * nchunk * DD;
    float acc = 0.f;
    for (int c = 0; c < nchunk; c++)
        acc += p[(size_t)c * DD + d];
    out[(size_t)g * DD + d] = acc * scale;
}

__global__ void resupd_kernel(float* __restrict__ res, const float* __restrict__ delta,
                              const float* __restrict__ gate, const float* __restrict__ pw, int p) {
    size_t i = (size_t)blockIdx.x * blockDim.x + threadIdx.x;
    res[i] += pw[p] * gate[i & 511] * delta[i];
}

__global__ void wg_kernel(const float* __restrict__ summary, const float* __restrict__ W,
                          const float* __restrict__ b, float* __restrict__ wg) {
    __shared__ float red[512];
    int tid = threadIdx.x;
    for (int r = 0; r < RR; r++) {
        red[tid] = summary[tid] * W[(size_t)r * DD + tid];
        __syncthreads();
        #pragma unroll
        for (int o = 256; o > 0; o >>= 1) { if (tid < o) red[tid] += red[tid + o]; __syncthreads(); }
        if (tid == 0) wg[r] = 1.f / (1.f + expf(-(red[0] + b[r])));
        __syncthreads();
    }
}

__global__ void regsupd_kernel(const float* __restrict__ summary, const float* __restrict__ Wp,
                               const float* __restrict__ wg, float* __restrict__ regs) {
    int r = blockIdx.x;
    int k = threadIdx.x;
    const float* W = Wp + (size_t)r * DD * DRR;
    float acc = 0.f;
    for (int d = 0; d < DD; d++)
        acc += summary[d] * W[(size_t)d * DRR + k];
    regs[r * DRR + k] += wg[r] * acc;
}

__global__ void bankcopy_kernel(const float* __restrict__ regs, float* __restrict__ banks, int p) {
    int j = threadIdx.x;
    banks[p * RDR + j] = regs[j];
}

__global__ void resmo_kernel(float* __restrict__ res, const float* __restrict__ mo) {
    size_t i = (size_t)blockIdx.x * blockDim.x + threadIdx.x;
    int d = (int)(i & 511);
    int b = (int)(i >> 20);
    res[i] += mo[(b << 9) + d];
}

// ---------------- host orchestration ----------------

extern "C" void kernel_launch(void* const* d_in, const int* in_sizes, int n_in,
                              void* d_out, int out_size) {
    const float* x        = (const float*)d_in[0];
    const float* reg_init = (const float*)d_in[1];
    const float* ffn_ln_s = (const float*)d_in[2];
    const float* ffn_ln_b = (const float*)d_in[3];
    const float* ffn_w1   = (const float*)d_in[4];
    const float* ffn_b1   = (const float*)d_in[5];
    const float* ffn_w2   = (const float*)d_in[6];
    const float* ffn_b2   = (const float*)d_in[7];
    const float* gate_w   = (const float*)d_in[8];
    const float* gate_b   = (const float*)d_in[9];
    const float* wproj_w  = (const float*)d_in[10];
    const float* wgate_w  = (const float*)d_in[11];
    const float* wgate_b  = (const float*)d_in[12];
    const float* s4_q     = (const float*)d_in[13];
    const float* s4_k     = (const float*)d_in[14];
    const float* s4_v     = (const float*)d_in[15];
    const float* s4_sum   = (const float*)d_in[16];
    const float* s4_ln_s  = (const float*)d_in[17];
    const float* s4_ln_b  = (const float*)d_in[18];
    const float* ms3_w    = (const float*)d_in[19];
    const float* ms3_b    = (const float*)d_in[20];
    const float* m4_q     = (const float*)d_in[21];
    const float* m4_k     = (const float*)d_in[22];
    const float* m4_v     = (const float*)d_in[23];
    const float* m4_out   = (const float*)d_in[24];
    const float* m4_ln_s  = (const float*)d_in[25];
    const float* m4_ln_b  = (const float*)d_in[26];
    const float* out_ln_s = (const float*)d_in[27];
    const float* out_ln_b = (const float*)d_in[28];

    float *res, *xn, *delta, *sc, *part, *q, *kq, *wxm, *summ, *regs, *gate, *wg;
    float *banks, *pw, *wxb, *ms1, *mo;
    __half *xnh, *xnl, *hh, *hl, *w1th, *w2th;
    cudaGetSymbolAddress((void**)&res,   g_res);
    cudaGetSymbolAddress((void**)&xn,    g_xn);
    cudaGetSymbolAddress((void**)&delta, g_delta);
    cudaGetSymbolAddress((void**)&sc,    g_sc);
    cudaGetSymbolAddress((void**)&part,  g_part);
    cudaGetSymbolAddress((void**)&q,     g_q);
    cudaGetSymbolAddress((void**)&kq,    g_kq);
    cudaGetSymbolAddress((void**)&wxm,   g_wxm);
    cudaGetSymbolAddress((void**)&summ,  g_summ);
    cudaGetSymbolAddress((void**)&regs,  g_regs);
    cudaGetSymbolAddress((void**)&gate,  g_gate);
    cudaGetSymbolAddress((void**)&wg,    g_wg);
    cudaGetSymbolAddress((void**)&banks, g_banks);
    cudaGetSymbolAddress((void**)&pw,    g_pw);
    cudaGetSymbolAddress((void**)&wxb,   g_wxb);
    cudaGetSymbolAddress((void**)&ms1,   g_ms1);
    cudaGetSymbolAddress((void**)&mo,    g_mo);
    cudaGetSymbolAddress((void**)&xnh,   g_xnh);
    cudaGetSymbolAddress((void**)&xnl,   g_xnl);
    cudaGetSymbolAddress((void**)&hh,    g_hh);
    cudaGetSymbolAddress((void**)&hl,    g_hl);
    cudaGetSymbolAddress((void**)&w1th,  g_w1th);
    cudaGetSymbolAddress((void**)&w2th,  g_w2th);

    const int ELEM = NTOK * DD;

    // weight transpose -> fp16 (per replay; cheap and deterministic)
    for (int ph = 0; ph < PHH; ph++) {
        dim3 blk(32, 32);
        dim3 g1(FF / 32, DD / 32);   // w1 [D,F] -> [F,D]
        transpose_half_kernel<<<g1, blk>>>(ffn_w1 + (size_t)ph * DD * FF,
                                           w1th + (size_t)ph * FF * DD, DD, FF);
        dim3 g2(DD / 32, FF / 32);   // w2 [F,D] -> [D,F]
        transpose_half_kernel<<<g2, blk>>>(ffn_w2 + (size_t)ph * FF * DD,
                                           w2th + (size_t)ph * DD * FF, FF, DD);
    }

    copy_kernel<<<ELEM / 256, 256>>>(x, res);
    passw_kernel<<<1, 32>>>(reg_init, ms3_w, ms3_b, pw);

    for (int p = 0; p < PP; p++) {
        // ---- S4 read (collapsed attention) ----
        qproj_kernel<<<2, 256>>>(banks, p * RDR, s4_q, q);
        matvec_kernel<<<512, 128>>>(s4_k, q, kq);
        ln_kernel<<<NTOK, 256>>>(res, xn, s4_ln_s, s4_ln_b, kq, sc);
        softmax_kernel<<<BB, 1024>>>(sc);
        wxpart_kernel<<<128, 512>>>(sc, xn, part);
        part_reduce_kernel<<<1, 512>>>(part, wxm, 128, 1.0f / BB);
        vecmat_kernel<<<2, 256>>>(wxm, s4_v, nullptr, nullptr, summ, DD, DD, 0);
        vecmat_kernel<<<3, 256>>>(summ, s4_sum, nullptr, reg_init, regs, DD, RDR, 0);

        for (int ph = 0; ph < PHH; ph++) {
            const int pp = p * PHH + ph;
            // FFN: LN -> split-fp16 GEMM (gelu, split out) -> split-fp16 GEMM (fp32 out)
            ln_fp16_kernel<<<NTOK, 256>>>(res, xnh, xnl,
                                          ffn_ln_s + (size_t)ph * DD,
                                          ffn_ln_b + (size_t)ph * DD);
            {
                dim3 grid(FF / 128, NTOK / 128);
                mmagemm_kernel<1><<<grid, 256>>>(xnh, xnl,
                                                 w1th + (size_t)ph * FF * DD,
                                                 ffn_b1 + (size_t)ph * FF,
                                                 nullptr, hh, hl, NTOK, FF, DD);
            }
            {
                dim3 grid(DD / 128, NTOK / 128);
                mmagemm_kernel<0><<<grid, 256>>>(hh, hl,
                                                 w2th + (size_t)ph * DD * FF,
                                                 ffn_b2 + (size_t)ph * DD,
                                                 delta, nullptr, nullptr, NTOK, DD, FF);
            }
            // summary = mean over tokens of delta
            colsum_part_kernel<<<128, 512>>>(delta, part);
            part_reduce_kernel<<<1, 512>>>(part, regs + RDR, 128, 1.0f / (float)NTOK);
            // gate = sigmoid([regs|summary] @ gate_w + gate_b)
            vecmat_kernel<<<2, 256>>>(regs, gate_w + (size_t)pp * (RDR + DD) * DD,
                                      gate_b + (size_t)pp * DD, nullptr, gate,
                                      RDR + DD, DD, 1);
            resupd_kernel<<<ELEM / 256, 256>>>(res, delta, gate, pw, p);
            // register update
            wg_kernel<<<1, 512>>>(regs + RDR, wgate_w + (size_t)pp * RR * DD,
                                  wgate_b + (size_t)pp * RR, wg);
            regsupd_kernel<<<RR, DRR>>>(regs + RDR, wproj_w + (size_t)pp * RR * DD * DRR,
                                        wg, regs);
        }
        bankcopy_kernel<<<1, RDR>>>(regs, banks, p);
    }

    // ---- MetaS4 ----
    qproj_kernel<<<2, 256>>>(banks, PP * RDR, m4_q, q);
    matvec_kernel<<<512, 128>>>(m4_k, q, kq);
    ln_kernel<<<NTOK, 256>>>(res, xn, m4_ln_s, m4_ln_b, kq, sc);
    softmax_kernel<<<BB, 1024>>>(sc);
    wxpart_kernel<<<128, 512>>>(sc, xn, part);
    part_reduce_kernel<<<BB, 512>>>(part, wxb, 32, 1.0f);
    for (int b = 0; b < BB; b++) {
        vecmat_kernel<<<2, 256>>>(wxb + (size_t)b * DD, m4_v, nullptr, nullptr,
                                  ms1 + (size_t)b * DD, DD, DD, 0);
        vecmat_kernel<<<2, 256>>>(ms1 + (size_t)b * DD, m4_out, nullptr, nullptr,
                                  mo + (size_t)b * DD, DD, DD, 0);
    }
    resmo_kernel<<<ELEM / 256, 256>>>(res, mo);

    // ---- final LayerNorm -> output ----
    ln_kernel<<<NTOK, 256>>>(res, (float*)d_out, out_ln_s, out_ln_b, nullptr, nullptr);
}

// round 5
// speedup vs baseline: 2.1324x; 1.1585x over previous
#include <cuda_runtime.h>
#include <cuda_fp16.h>
#include <math.h>
#include <stdint.h>

// ---------------- problem constants ----------------
#define BB 4
#define LL 2048
#define DD 512
#define DRR 256
#define RR 3
#define PP 5
#define PHH 3
#define FF 1536
#define NTOK (BB*LL)            // 8192
#define RDR (RR*DRR)            // 768

// ---------------- device scratch ----------------
__device__ __align__(256) float g_res[NTOK*DD];
__device__ __align__(256) float g_xn[NTOK*DD];
__device__ __align__(256) float g_delta[NTOK*DD];
__device__ __align__(256) float g_sc[NTOK];
__device__ __align__(256) float g_part[128*DD];
__device__ __align__(256) float g_q[DD];
__device__ __align__(256) float g_kq[DD];
__device__ __align__(256) float g_wxm[DD];
__device__ __align__(256) float g_summ[DD];
__device__ __align__(256) float g_regs[RDR + DD];   // gin = [regs | summary]
__device__ __align__(256) float g_gate[DD];
__device__ __align__(256) float g_wg[16];
__device__ __align__(256) float g_banks[PP*RDR];
__device__ __align__(256) float g_pw[16];
__device__ __align__(256) float g_wxb[BB*DD];
__device__ __align__(256) float g_ms1[BB*DD];
__device__ __align__(256) float g_mo[BB*DD];

__device__ __align__(256) __half g_xnh[NTOK*DD];
__device__ __align__(256) __half g_hh[NTOK*FF];
__device__ __align__(256) __half g_w1th[PHH*FF*DD];
__device__ __align__(256) __half g_w2th[PHH*DD*FF];

// ---------------- PTX helpers (arch-agnostic: sm_80+) ----------------
__device__ __forceinline__ uint32_t smem_u32(const void* p) {
    return (uint32_t)__cvta_generic_to_shared(p);
}
__device__ __forceinline__ void cpasync16(uint32_t dst, const void* src) {
    asm volatile("cp.async.cg.shared.global [%0], [%1], 16;" :: "r"(dst), "l"(src) : "memory");
}
__device__ __forceinline__ void cp_commit() {
    asm volatile("cp.async.commit_group;" ::: "memory");
}
__device__ __forceinline__ void cp_wait1() {
    asm volatile("cp.async.wait_group 1;" ::: "memory");
}
__device__ __forceinline__ void ldsm4(uint32_t* r, uint32_t addr) {
    asm volatile("ldmatrix.sync.aligned.m8n8.x4.shared.b16 {%0,%1,%2,%3}, [%4];"
                 : "=r"(r[0]), "=r"(r[1]), "=r"(r[2]), "=r"(r[3]) : "r"(addr));
}
__device__ __forceinline__ void mma16816(float* c, const uint32_t* a, uint32_t b0, uint32_t b1) {
    asm volatile(
        "mma.sync.aligned.m16n8k16.row.col.f32.f16.f16.f32 "
        "{%0,%1,%2,%3}, {%4,%5,%6,%7}, {%8,%9}, {%0,%1,%2,%3};"
        : "+f"(c[0]), "+f"(c[1]), "+f"(c[2]), "+f"(c[3])
        : "r"(a[0]), "r"(a[1]), "r"(a[2]), "r"(a[3]), "r"(b0), "r"(b1));
}

// ---------------- fp16 GEMM via mma.sync (single K-sweep, single term) ----------------
// C[M,N] = A[M,K] @ B^T.  A rows fp16(A), B rows [N,K] fp16(B). fp32 accumulate.
// OUTMODE 0: Cf = acc + bias. OUTMODE 1: Ch = fp16(gelu(acc+bias)).
// CTA tile 128x128, 256 thr (8 warps: 4m x 2n, warp tile 32x64), kchunk 32,
// 3-stage cp.async pipeline, XOR-swizzled K-major smem, ldmatrix.x4 operands.

#define STAGE_BYTES 16384           // A 8KB + B 8KB
#define NSTAGE 3

template <int OUTMODE>
__global__ void __launch_bounds__(256, 2)
mmagemm_kernel(const __half* __restrict__ Ah, const __half* __restrict__ Bh,
               const float* __restrict__ bias,
               float* __restrict__ Cf, __half* __restrict__ Ch,
               int M, int N, int K) {
    __shared__ __align__(128) unsigned char smem[NSTAGE * STAGE_BYTES];   // 48KB

    const int tid  = threadIdx.x;
    const int wid  = tid >> 5;
    const int lane = tid & 31;
    const int n0 = blockIdx.x * 128;
    const int m0 = blockIdx.y * 128;

    const int NIT = K >> 5;             // k32 chunks, single sweep

    // this thread's two 16B segments of each 8KB tile:
    // seg s (0..511): row = s>>2, c = s&3; swizzled column c^(row&3)
    const int sg0 = tid, sg1 = tid + 256;
    const int r0s = sg0 >> 2, c0s = sg0 & 3;
    const int r1s = sg1 >> 2, c1s = sg1 & 3;
    const uint32_t smem_base = smem_u32(smem);
    const uint32_t dA0 = (uint32_t)(((r0s << 2) + (c0s ^ (r0s & 3))) << 4);
    const uint32_t dA1 = (uint32_t)(((r1s << 2) + (c1s ^ (r1s & 3))) << 4);

    auto prefetch = [&](int it) {
        const int k0 = it << 5;
        const uint32_t st = smem_base + (uint32_t)(it % NSTAGE) * STAGE_BYTES;
        cpasync16(st + dA0,         Ah + (size_t)(m0 + r0s) * K + k0 + c0s * 8);
        cpasync16(st + dA1,         Ah + (size_t)(m0 + r1s) * K + k0 + c1s * 8);
        cpasync16(st + 8192 + dA0,  Bh + (size_t)(n0 + r0s) * K + k0 + c0s * 8);
        cpasync16(st + 8192 + dA1,  Bh + (size_t)(n0 + r1s) * K + k0 + c1s * 8);
        cp_commit();
    };

    float acc[2][8][4];
    #pragma unroll
    for (int i = 0; i < 2; i++)
        #pragma unroll
        for (int j = 0; j < 8; j++)
            #pragma unroll
            for (int t = 0; t < 4; t++) acc[i][j][t] = 0.f;

    const int wm = (wid & 3) * 32;      // warp m-offset in tile
    const int wn = (wid >> 2) * 64;     // warp n-offset in tile
    const int lrow = lane & 15;
    const int lseg = lane >> 4;

    prefetch(0);
    prefetch(1);

    #pragma unroll 1
    for (int it = 0; it < NIT; it++) {
        cp_wait1();
        __syncthreads();
        if (it + 2 < NIT) prefetch(it + 2);

        const uint32_t st = smem_base + (uint32_t)(it % NSTAGE) * STAGE_BYTES;
        #pragma unroll
        for (int kk = 0; kk < 2; kk++) {            // two k16 per chunk
            uint32_t af[2][4];
            #pragma unroll
            for (int i = 0; i < 2; i++) {
                int row = wm + i * 16 + lrow;
                int seg = kk * 2 + lseg;
                ldsm4(af[i], st + (uint32_t)(((row << 2) + (seg ^ (row & 3))) << 4));
            }
            uint32_t bf[4][4];
            #pragma unroll
            for (int g = 0; g < 4; g++) {
                int row = wn + g * 16 + lrow;
                int seg = kk * 2 + lseg;
                ldsm4(bf[g], st + 8192u + (uint32_t)(((row << 2) + (seg ^ (row & 3))) << 4));
            }
            #pragma unroll
            for (int i = 0; i < 2; i++)
                #pragma unroll
                for (int j = 0; j < 8; j++) {
                    int g = j >> 1, w = j & 1;
                    mma16816(acc[i][j], af[i], bf[g][w], bf[g][w + 2]);
                }
        }
    }

    // ---- epilogue: straight from register fragments ----
    const int l4 = lane >> 2;
    const int l2 = (lane & 3) * 2;
    #pragma unroll
    for (int i = 0; i < 2; i++) {
        #pragma unroll
        for (int j = 0; j < 8; j++) {
            const int col  = n0 + wn + j * 8 + l2;
            const int row0 = m0 + wm + i * 16 + l4;
            const float b0v = bias[col];
            const float b1v = bias[col + 1];
            float v00 = acc[i][j][0] + b0v, v01 = acc[i][j][1] + b1v;   // row0
            float v10 = acc[i][j][2] + b0v, v11 = acc[i][j][3] + b1v;   // row0+8
            if (OUTMODE == 0) {
                *(float2*)(Cf + (size_t)row0 * N + col)       = make_float2(v00, v01);
                *(float2*)(Cf + (size_t)(row0 + 8) * N + col) = make_float2(v10, v11);
            } else {
                float vv[4] = {v00, v01, v10, v11};
                unsigned short hh_[4];
                #pragma unroll
                for (int t = 0; t < 4; t++) {
                    float v = vv[t];
                    v = 0.5f * v * (1.0f + erff(v * 0.70710678118654752f));
                    hh_[t] = __half_as_ushort(__float2half_rn(v));
                }
                *(ushort2*)((unsigned short*)Ch + (size_t)row0 * N + col)       = make_ushort2(hh_[0], hh_[1]);
                *(ushort2*)((unsigned short*)Ch + (size_t)(row0 + 8) * N + col) = make_ushort2(hh_[2], hh_[3]);
            }
        }
    }
}

// ---------------- transpose + fp16: in[Rr,Cc] -> out[Cc,Rr] ----------------
__global__ void transpose_half_kernel(const float* __restrict__ in,
                                      __half* __restrict__ oh,
                                      int Rr, int Cc) {
    __shared__ float t[32][33];
    int r = blockIdx.y * 32 + threadIdx.y;
    int c = blockIdx.x * 32 + threadIdx.x;
    t[threadIdx.y][threadIdx.x] = in[(size_t)r * Cc + c];
    __syncthreads();
    int orow = blockIdx.x * 32 + threadIdx.y;
    int ocol = blockIdx.y * 32 + threadIdx.x;
    oh[(size_t)orow * Rr + ocol] = __float2half_rn(t[threadIdx.x][threadIdx.y]);
}

// ---------------- small kernels (proven) ----------------

__global__ void copy_kernel(const float* __restrict__ src, float* __restrict__ dst) {
    size_t i = (size_t)blockIdx.x * blockDim.x + threadIdx.x;
    dst[i] = src[i];
}

__global__ void passw_kernel(const float* __restrict__ reg_init,
                             const float* __restrict__ W,
                             const float* __restrict__ b,
                             float* __restrict__ pw) {
    int p = threadIdx.x;
    if (p >= PP) return;
    float acc = 0.f;
    for (int i = 0; i < PP * RDR; i++)
        acc += reg_init[i % RDR] * W[i * PP + p];
    pw[p] = 1.f / (1.f + expf(-(acc + b[p])));
}

__global__ void qproj_kernel(const float* __restrict__ bank, int n,
                             const float* __restrict__ Wq, float* __restrict__ q) {
    int d = blockIdx.x * blockDim.x + threadIdx.x;
    if (d >= DD) return;
    float acc = 0.f;
    for (int i = 0; i < n; i++)
        acc += bank[i] * Wq[(size_t)i * DD + d];
    q[d] = acc;
}

__global__ void matvec_kernel(const float* __restrict__ M,
                              const float* __restrict__ v,
                              float* __restrict__ out) {
    __shared__ float red[128];
    int r = blockIdx.x;
    int tid = threadIdx.x;
    float acc = 0.f;
    for (int j = tid; j < DD; j += 128)
        acc += M[(size_t)r * DD + j] * v[j];
    red[tid] = acc; __syncthreads();
    for (int o = 64; o > 0; o >>= 1) {
        if (tid < o) red[tid] += red[tid + o];
        __syncthreads();
    }
    if (tid == 0) out[r] = red[0];
}

__global__ void vecmat_kernel(const float* __restrict__ v, const float* __restrict__ M,
                              const float* __restrict__ bias, const float* __restrict__ init,
                              float* __restrict__ out, int nrow, int ncol, int act) {
    int j = blockIdx.x * blockDim.x + threadIdx.x;
    if (j >= ncol) return;
    float acc = 0.f;
    for (int d = 0; d < nrow; d++)
        acc += v[d] * M[(size_t)d * ncol + j];
    if (bias) acc += bias[j];
    if (init) acc += init[j];
    if (act == 1) acc = 1.f / (1.f + expf(-acc));
    out[j] = acc;
}

__global__ void ln_kernel(const float* __restrict__ in, float* __restrict__ out,
                          const float* __restrict__ gs, const float* __restrict__ gb,
                          const float* __restrict__ kq, float* __restrict__ score) {
    __shared__ float red[256];
    int t = blockIdx.x;
    int tid = threadIdx.x;
    const float* row = in + (size_t)t * DD;
    float x0 = row[tid];
    float x1 = row[tid + 256];
    red[tid] = x0 + x1; __syncthreads();
    #pragma unroll
    for (int o = 128; o > 0; o >>= 1) { if (tid < o) red[tid] += red[tid + o]; __syncthreads(); }
    float mean = red[0] * (1.0f / 512.0f);
    __syncthreads();
    float d0 = x0 - mean, d1 = x1 - mean;
    red[tid] = d0 * d0 + d1 * d1; __syncthreads();
    #pragma unroll
    for (int o = 128; o > 0; o >>= 1) { if (tid < o) red[tid] += red[tid + o]; __syncthreads(); }
    float rstd = rsqrtf(red[0] * (1.0f / 512.0f) + 1e-5f);
    __syncthreads();
    float y0 = d0 * rstd * gs[tid] + gb[tid];
    float y1 = d1 * rstd * gs[tid + 256] + gb[tid + 256];
    out[(size_t)t * DD + tid] = y0;
    out[(size_t)t * DD + tid + 256] = y1;
    if (kq) {
        red[tid] = y0 * kq[tid] + y1 * kq[tid + 256]; __syncthreads();
        #pragma unroll
        for (int o = 128; o > 0; o >>= 1) { if (tid < o) red[tid] += red[tid + o]; __syncthreads(); }
        if (tid == 0) score[t] = red[0] * 0.044194173824159216f;
    }
}

// LayerNorm emitting fp16 (for the FFN GEMM input)
__global__ void ln_fp16_kernel(const float* __restrict__ in,
                               __half* __restrict__ oh,
                               const float* __restrict__ gs, const float* __restrict__ gb) {
    __shared__ float red[256];
    int t = blockIdx.x;
    int tid = threadIdx.x;
    const float* row = in + (size_t)t * DD;
    float x0 = row[tid];
    float x1 = row[tid + 256];
    red[tid] = x0 + x1; __syncthreads();
    #pragma unroll
    for (int o = 128; o > 0; o >>= 1) { if (tid < o) red[tid] += red[tid + o]; __syncthreads(); }
    float mean = red[0] * (1.0f / 512.0f);
    __syncthreads();
    float d0 = x0 - mean, d1 = x1 - mean;
    red[tid] = d0 * d0 + d1 * d1; __syncthreads();
    #pragma unroll
    for (int o = 128; o > 0; o >>= 1) { if (tid < o) red[tid] += red[tid + o]; __syncthreads(); }
    float rstd = rsqrtf(red[0] * (1.0f / 512.0f) + 1e-5f);
    float y0 = d0 * rstd * gs[tid] + gb[tid];
    float y1 = d1 * rstd * gs[tid + 256] + gb[tid + 256];
    oh[(size_t)t * DD + tid]       = __float2half_rn(y0);
    oh[(size_t)t * DD + tid + 256] = __float2half_rn(y1);
}

__global__ void softmax_kernel(float* __restrict__ sc) {
    __shared__ float red[1024];
    int b = blockIdx.x;
    float* p = sc + (size_t)b * LL;
    int tid = threadIdx.x;
    float v0 = p[tid], v1 = p[tid + 1024];
    red[tid] = fmaxf(v0, v1); __syncthreads();
    #pragma unroll
    for (int o = 512; o > 0; o >>= 1) { if (tid < o) red[tid] = fmaxf(red[tid], red[tid + o]); __syncthreads(); }
    float mx = red[0];
    __syncthreads();
    float e0 = expf(v0 - mx), e1 = expf(v1 - mx);
    red[tid] = e0 + e1; __syncthreads();
    #pragma unroll
    for (int o = 512; o > 0; o >>= 1) { if (tid < o) red[tid] += red[tid + o]; __syncthreads(); }
    float inv = 1.f / red[0];
    p[tid] = e0 * inv;
    p[tid + 1024] = e1 * inv;
}

__global__ void wxpart_kernel(const float* __restrict__ a, const float* __restrict__ xn,
                              float* __restrict__ part) {
    int d = threadIdx.x;
    int blk = blockIdx.x;
    int row0 = blk * 64;
    float acc = 0.f;
    for (int r = row0; r < row0 + 64; r++)
        acc += a[r] * xn[(size_t)r * DD + d];
    part[(size_t)blk * DD + d] = acc;
}

__global__ void colsum_part_kernel(const float* __restrict__ delta, float* __restrict__ part) {
    int d = threadIdx.x;
    int c = blockIdx.x;
    float acc = 0.f;
    for (int r = c * 64; r < (c + 1) * 64; r++)
        acc += delta[(size_t)r * DD + d];
    part[(size_t)c * DD + d] = acc;
}

__global__ void part_reduce_kernel(const float* __restrict__ part, float* __restrict__ out,
                                   int nchunk, float scale) {
    int d = threadIdx.x;
    int g = blockIdx.x;
    const float* p = part + (size_t)g * nchunk * DD;
    float acc = 0.f;
    for (int c = 0; c < nchunk; c++)
        acc += p[(size_t)c * DD + d];
    out[(size_t)g * DD + d] = acc * scale;
}

__global__ void resupd_kernel(float* __restrict__ res, const float* __restrict__ delta,
                              const float* __restrict__ gate, const float* __restrict__ pw, int p) {
    size_t i = (size_t)blockIdx.x * blockDim.x + threadIdx.x;
    res[i] += pw[p] * gate[i & 511] * delta[i];
}

__global__ void wg_kernel(const float* __restrict__ summary, const float* __restrict__ W,
                          const float* __restrict__ b, float* __restrict__ wg) {
    __shared__ float red[512];
    int tid = threadIdx.x;
    for (int r = 0; r < RR; r++) {
        red[tid] = summary[tid] * W[(size_t)r * DD + tid];
        __syncthreads();
        #pragma unroll
        for (int o = 256; o > 0; o >>= 1) { if (tid < o) red[tid] += red[tid + o]; __syncthreads(); }
        if (tid == 0) wg[r] = 1.f / (1.f + expf(-(red[0] + b[r])));
        __syncthreads();
    }
}

__global__ void regsupd_kernel(const float* __restrict__ summary, const float* __restrict__ Wp,
                               const float* __restrict__ wg, float* __restrict__ regs) {
    int r = blockIdx.x;
    int k = threadIdx.x;
    const float* W = Wp + (size_t)r * DD * DRR;
    float acc = 0.f;
    for (int d = 0; d < DD; d++)
        acc += summary[d] * W[(size_t)d * DRR + k];
    regs[r * DRR + k] += wg[r] * acc;
}

__global__ void bankcopy_kernel(const float* __restrict__ regs, float* __restrict__ banks, int p) {
    int j = threadIdx.x;
    banks[p * RDR + j] = regs[j];
}

__global__ void resmo_kernel(float* __restrict__ res, const float* __restrict__ mo) {
    size_t i = (size_t)blockIdx.x * blockDim.x + threadIdx.x;
    int d = (int)(i & 511);
    int b = (int)(i >> 20);
    res[i] += mo[(b << 9) + d];
}

// ---------------- host orchestration ----------------

extern "C" void kernel_launch(void* const* d_in, const int* in_sizes, int n_in,
                              void* d_out, int out_size) {
    const float* x        = (const float*)d_in[0];
    const float* reg_init = (const float*)d_in[1];
    const float* ffn_ln_s = (const float*)d_in[2];
    const float* ffn_ln_b = (const float*)d_in[3];
    const float* ffn_w1   = (const float*)d_in[4];
    const float* ffn_b1   = (const float*)d_in[5];
    const float* ffn_w2   = (const float*)d_in[6];
    const float* ffn_b2   = (const float*)d_in[7];
    const float* gate_w   = (const float*)d_in[8];
    const float* gate_b   = (const float*)d_in[9];
    const float* wproj_w  = (const float*)d_in[10];
    const float* wgate_w  = (const float*)d_in[11];
    const float* wgate_b  = (const float*)d_in[12];
    const float* s4_q     = (const float*)d_in[13];
    const float* s4_k     = (const float*)d_in[14];
    const float* s4_v     = (const float*)d_in[15];
    const float* s4_sum   = (const float*)d_in[16];
    const float* s4_ln_s  = (const float*)d_in[17];
    const float* s4_ln_b  = (const float*)d_in[18];
    const float* ms3_w    = (const float*)d_in[19];
    const float* ms3_b    = (const float*)d_in[20];
    const float* m4_q     = (const float*)d_in[21];
    const float* m4_k     = (const float*)d_in[22];
    const float* m4_v     = (const float*)d_in[23];
    const float* m4_out   = (const float*)d_in[24];
    const float* m4_ln_s  = (const float*)d_in[25];
    const float* m4_ln_b  = (const float*)d_in[26];
    const float* out_ln_s = (const float*)d_in[27];
    const float* out_ln_b = (const float*)d_in[28];

    float *res, *xn, *delta, *sc, *part, *q, *kq, *wxm, *summ, *regs, *gate, *wg;
    float *banks, *pw, *wxb, *ms1, *mo;
    __half *xnh, *hh, *w1th, *w2th;
    cudaGetSymbolAddress((void**)&res,   g_res);
    cudaGetSymbolAddress((void**)&xn,    g_xn);
    cudaGetSymbolAddress((void**)&delta, g_delta);
    cudaGetSymbolAddress((void**)&sc,    g_sc);
    cudaGetSymbolAddress((void**)&part,  g_part);
    cudaGetSymbolAddress((void**)&q,     g_q);
    cudaGetSymbolAddress((void**)&kq,    g_kq);
    cudaGetSymbolAddress((void**)&wxm,   g_wxm);
    cudaGetSymbolAddress((void**)&summ,  g_summ);
    cudaGetSymbolAddress((void**)&regs,  g_regs);
    cudaGetSymbolAddress((void**)&gate,  g_gate);
    cudaGetSymbolAddress((void**)&wg,    g_wg);
    cudaGetSymbolAddress((void**)&banks, g_banks);
    cudaGetSymbolAddress((void**)&pw,    g_pw);
    cudaGetSymbolAddress((void**)&wxb,   g_wxb);
    cudaGetSymbolAddress((void**)&ms1,   g_ms1);
    cudaGetSymbolAddress((void**)&mo,    g_mo);
    cudaGetSymbolAddress((void**)&xnh,   g_xnh);
    cudaGetSymbolAddress((void**)&hh,    g_hh);
    cudaGetSymbolAddress((void**)&w1th,  g_w1th);
    cudaGetSymbolAddress((void**)&w2th,  g_w2th);

    const int ELEM = NTOK * DD;

    // weight transpose -> fp16 (per replay; cheap and deterministic)
    for (int ph = 0; ph < PHH; ph++) {
        dim3 blk(32, 32);
        dim3 g1(FF / 32, DD / 32);   // w1 [D,F] -> [F,D]
        transpose_half_kernel<<<g1, blk>>>(ffn_w1 + (size_t)ph * DD * FF,
                                           w1th + (size_t)ph * FF * DD, DD, FF);
        dim3 g2(DD / 32, FF / 32);   // w2 [F,D] -> [D,F]
        transpose_half_kernel<<<g2, blk>>>(ffn_w2 + (size_t)ph * FF * DD,
                                           w2th + (size_t)ph * DD * FF, FF, DD);
    }

    copy_kernel<<<ELEM / 256, 256>>>(x, res);
    passw_kernel<<<1, 32>>>(reg_init, ms3_w, ms3_b, pw);

    for (int p = 0; p < PP; p++) {
        // ---- S4 read (collapsed attention) ----
        qproj_kernel<<<2, 256>>>(banks, p * RDR, s4_q, q);
        matvec_kernel<<<512, 128>>>(s4_k, q, kq);
        ln_kernel<<<NTOK, 256>>>(res, xn, s4_ln_s, s4_ln_b, kq, sc);
        softmax_kernel<<<BB, 1024>>>(sc);
        wxpart_kernel<<<128, 512>>>(sc, xn, part);
        part_reduce_kernel<<<1, 512>>>(part, wxm, 128, 1.0f / BB);
        vecmat_kernel<<<2, 256>>>(wxm, s4_v, nullptr, nullptr, summ, DD, DD, 0);
        vecmat_kernel<<<3, 256>>>(summ, s4_sum, nullptr, reg_init, regs, DD, RDR, 0);

        for (int ph = 0; ph < PHH; ph++) {
            const int pp = p * PHH + ph;
            // FFN: LN -> fp16 GEMM (gelu, fp16 out) -> fp16 GEMM (fp32 out)
            ln_fp16_kernel<<<NTOK, 256>>>(res, xnh,
                                          ffn_ln_s + (size_t)ph * DD,
                                          ffn_ln_b + (size_t)ph * DD);
            {
                dim3 grid(FF / 128, NTOK / 128);
                mmagemm_kernel<1><<<grid, 256>>>(xnh,
                                                 w1th + (size_t)ph * FF * DD,
                                                 ffn_b1 + (size_t)ph * FF,
                                                 nullptr, hh, NTOK, FF, DD);
            }
            {
                dim3 grid(DD / 128, NTOK / 128);
                mmagemm_kernel<0><<<grid, 256>>>(hh,
                                                 w2th + (size_t)ph * DD * FF,
                                                 ffn_b2 + (size_t)ph * DD,
                                                 delta, nullptr, NTOK, DD, FF);
            }
            // summary = mean over tokens of delta
            colsum_part_kernel<<<128, 512>>>(delta, part);
            part_reduce_kernel<<<1, 512>>>(part, regs + RDR, 128, 1.0f / (float)NTOK);
            // gate = sigmoid([regs|summary] @ gate_w + gate_b)
            vecmat_kernel<<<2, 256>>>(regs, gate_w + (size_t)pp * (RDR + DD) * DD,
                                      gate_b + (size_t)pp * DD, nullptr, gate,
                                      RDR + DD, DD, 1);
            resupd_kernel<<<ELEM / 256, 256>>>(res, delta, gate, pw, p);
            // register update
            wg_kernel<<<1, 512>>>(regs + RDR, wgate_w + (size_t)pp * RR * DD,
                                  wgate_b + (size_t)pp * RR, wg);
            regsupd_kernel<<<RR, DRR>>>(regs + RDR, wproj_w + (size_t)pp * RR * DD * DRR,
                                        wg, regs);
        }
        bankcopy_kernel<<<1, RDR>>>(regs, banks, p);
    }

    // ---- MetaS4 ----
    qproj_kernel<<<2, 256>>>(banks, PP * RDR, m4_q, q);
    matvec_kernel<<<512, 128>>>(m4_k, q, kq);
    ln_kernel<<<NTOK, 256>>>(res, xn, m4_ln_s, m4_ln_b, kq, sc);
    softmax_kernel<<<BB, 1024>>>(sc);
    wxpart_kernel<<<128, 512>>>(sc, xn, part);
    part_reduce_kernel<<<BB, 512>>>(part, wxb, 32, 1.0f);
    for (int b = 0; b < BB; b++) {
        vecmat_kernel<<<2, 256>>>(wxb + (size_t)b * DD, m4_v, nullptr, nullptr,
                                  ms1 + (size_t)b * DD, DD, DD, 0);
        vecmat_kernel<<<2, 256>>>(ms1 + (size_t)b * DD, m4_out, nullptr, nullptr,
                                  mo + (size_t)b * DD, DD, DD, 0);
    }
    resmo_kernel<<<ELEM / 256, 256>>>(res, mo);

    // ---- final LayerNorm -> output ----
    ln_kernel<<<NTOK, 256>>>(res, (float*)d_out, out_ln_s, out_ln_b, nullptr, nullptr);
}

// round 6
// speedup vs baseline: 2.5704x; 1.2054x over previous
#include <cuda_runtime.h>
#include <cuda_fp16.h>
#include <math.h>
#include <stdint.h>

// ---------------- problem constants ----------------
#define BB 4
#define LL 2048
#define DD 512
#define DRR 256
#define RR 3
#define PP 5
#define PHH 3
#define FF 1536
#define NTOK (BB*LL)            // 8192
#define RDR (RR*DRR)            // 768

// ---------------- device scratch ----------------
__device__ __align__(256) float g_res[NTOK*DD];
__device__ __align__(256) float g_xn[NTOK*DD];
__device__ __align__(256) float g_delta[NTOK*DD];
__device__ __align__(256) float g_sc[NTOK];
__device__ __align__(256) float g_part[128*DD];
__device__ __align__(256) float g_q[DD];
__device__ __align__(256) float g_kq[DD];
__device__ __align__(256) float g_wxm[DD];
__device__ __align__(256) float g_summ[DD];
__device__ __align__(256) float g_regs[RDR + DD];   // gin = [regs | summary]
__device__ __align__(256) float g_gate[DD];
__device__ __align__(256) float g_wg[16];
__device__ __align__(256) float g_banks[PP*RDR];
__device__ __align__(256) float g_pw[16];
__device__ __align__(256) float g_wxb[BB*DD];
__device__ __align__(256) float g_ms1[BB*DD];
__device__ __align__(256) float g_mo[BB*DD];

__device__ __align__(256) __half g_xnh[NTOK*DD];
__device__ __align__(256) __half g_hh[NTOK*FF];
__device__ __align__(256) __half g_w1th[PHH*FF*DD];
__device__ __align__(256) __half g_w2th[PHH*DD*FF];

// ---------------- PTX helpers (arch-agnostic: sm_80+) ----------------
__device__ __forceinline__ uint32_t smem_u32(const void* p) {
    return (uint32_t)__cvta_generic_to_shared(p);
}
__device__ __forceinline__ void cpasync16(uint32_t dst, const void* src) {
    asm volatile("cp.async.cg.shared.global [%0], [%1], 16;" :: "r"(dst), "l"(src) : "memory");
}
__device__ __forceinline__ void cp_commit() {
    asm volatile("cp.async.commit_group;" ::: "memory");
}
__device__ __forceinline__ void cp_wait1() {
    asm volatile("cp.async.wait_group 1;" ::: "memory");
}
__device__ __forceinline__ void ldsm4(uint32_t* r, uint32_t addr) {
    asm volatile("ldmatrix.sync.aligned.m8n8.x4.shared.b16 {%0,%1,%2,%3}, [%4];"
                 : "=r"(r[0]), "=r"(r[1]), "=r"(r[2]), "=r"(r[3]) : "r"(addr));
}
__device__ __forceinline__ void mma16816(float* c, const uint32_t* a, uint32_t b0, uint32_t b1) {
    asm volatile(
        "mma.sync.aligned.m16n8k16.row.col.f32.f16.f16.f32 "
        "{%0,%1,%2,%3}, {%4,%5,%6,%7}, {%8,%9}, {%0,%1,%2,%3};"
        : "+f"(c[0]), "+f"(c[1]), "+f"(c[2]), "+f"(c[3])
        : "r"(a[0]), "r"(a[1]), "r"(a[2]), "r"(a[3]), "r"(b0), "r"(b1));
}

// ---------------- fp16 GEMM via mma.sync (single K-sweep) ----------------
// C[M,N] = A[M,K] @ B^T. fp32 accumulate.
// OUTMODE 0: Cf = acc + bias. OUTMODE 1: Ch = fp16(gelu(acc+bias)).
// CTA tile 128x128, 256 thr (8 warps: 4m x 2n, warp tile 32x64), kchunk 64,
// 2-stage cp.async pipeline (64KB dynamic smem), XOR-swizzled K-major smem.
// Tile layout: 128 rows x 128B (64 halfs); seg c of row: offset row*128 + ((c^(row&7))<<4)

#define STAGE_BYTES 32768           // A 16KB + B 16KB
#define CHUNK_K 64

template <int OUTMODE>
__global__ void __launch_bounds__(256, 2)
mmagemm_kernel(const __half* __restrict__ Ah, const __half* __restrict__ Bh,
               const float* __restrict__ bias,
               float* __restrict__ Cf, __half* __restrict__ Ch,
               int M, int N, int K) {
    extern __shared__ __align__(128) unsigned char smem[];   // 2 * 32KB

    const int tid  = threadIdx.x;
    const int wid  = tid >> 5;
    const int lane = tid & 31;
    const int n0 = blockIdx.x * 128;
    const int m0 = blockIdx.y * 128;

    const int NIT = K >> 6;             // k64 chunks

    const uint32_t smem_base = smem_u32(smem);

    // per-thread load map: 4 segments of 16B for A tile, same for B tile
    int lrowA[4]; int lcA[4]; uint32_t ldst[4];
    #pragma unroll
    for (int u = 0; u < 4; u++) {
        int s = tid + u * 256;          // 0..1023
        int row = s >> 3, c = s & 7;
        lrowA[u] = row; lcA[u] = c;
        ldst[u] = (uint32_t)(row * 128 + ((c ^ (row & 7)) << 4));
    }

    auto prefetch = [&](int it) {
        const int k0 = it << 6;
        const uint32_t st = smem_base + (uint32_t)(it & 1) * STAGE_BYTES;
        #pragma unroll
        for (int u = 0; u < 4; u++)
            cpasync16(st + ldst[u], Ah + (size_t)(m0 + lrowA[u]) * K + k0 + lcA[u] * 8);
        #pragma unroll
        for (int u = 0; u < 4; u++)
            cpasync16(st + 16384 + ldst[u], Bh + (size_t)(n0 + lrowA[u]) * K + k0 + lcA[u] * 8);
        cp_commit();
    };

    float acc[2][8][4];
    #pragma unroll
    for (int i = 0; i < 2; i++)
        #pragma unroll
        for (int j = 0; j < 8; j++)
            #pragma unroll
            for (int t = 0; t < 4; t++) acc[i][j][t] = 0.f;

    const int wm = (wid & 3) * 32;      // warp m-offset
    const int wn = (wid >> 2) * 64;     // warp n-offset
    const int lrow = lane & 15;
    const int lseg = lane >> 4;

    prefetch(0);
    if (NIT > 1) prefetch(1);

    #pragma unroll 1
    for (int it = 0; it < NIT; it++) {
        cp_wait1();
        __syncthreads();

        const uint32_t st = smem_base + (uint32_t)(it & 1) * STAGE_BYTES;
        #pragma unroll
        for (int kk = 0; kk < 4; kk++) {            // four k16 per chunk
            uint32_t af[2][4];
            #pragma unroll
            for (int i = 0; i < 2; i++) {
                int row = wm + i * 16 + lrow;
                int seg = kk * 2 + lseg;
                ldsm4(af[i], st + (uint32_t)(row * 128 + (((seg ^ (row & 7))) << 4)));
            }
            uint32_t bf[4][4];
            #pragma unroll
            for (int g = 0; g < 4; g++) {
                int row = wn + g * 16 + lrow;
                int seg = kk * 2 + lseg;
                ldsm4(bf[g], st + 16384u + (uint32_t)(row * 128 + (((seg ^ (row & 7))) << 4)));
            }
            #pragma unroll
            for (int i = 0; i < 2; i++)
                #pragma unroll
                for (int j = 0; j < 8; j++) {
                    int g = j >> 1, w = j & 1;
                    mma16816(acc[i][j], af[i], bf[g][w], bf[g][w + 2]);
                }
        }
        __syncthreads();
        if (it + 2 < NIT) prefetch(it + 2);
    }

    // ---- epilogue: straight from register fragments ----
    const int l4 = lane >> 2;
    const int l2 = (lane & 3) * 2;
    #pragma unroll
    for (int i = 0; i < 2; i++) {
        #pragma unroll
        for (int j = 0; j < 8; j++) {
            const int col  = n0 + wn + j * 8 + l2;
            const int row0 = m0 + wm + i * 16 + l4;
            const float b0v = bias[col];
            const float b1v = bias[col + 1];
            float v00 = acc[i][j][0] + b0v, v01 = acc[i][j][1] + b1v;   // row0
            float v10 = acc[i][j][2] + b0v, v11 = acc[i][j][3] + b1v;   // row0+8
            if (OUTMODE == 0) {
                *(float2*)(Cf + (size_t)row0 * N + col)       = make_float2(v00, v01);
                *(float2*)(Cf + (size_t)(row0 + 8) * N + col) = make_float2(v10, v11);
            } else {
                float vv[4] = {v00, v01, v10, v11};
                unsigned short hh_[4];
                #pragma unroll
                for (int t = 0; t < 4; t++) {
                    float v = vv[t];
                    v = 0.5f * v * (1.0f + erff(v * 0.70710678118654752f));
                    hh_[t] = __half_as_ushort(__float2half_rn(v));
                }
                *(ushort2*)((unsigned short*)Ch + (size_t)row0 * N + col)       = make_ushort2(hh_[0], hh_[1]);
                *(ushort2*)((unsigned short*)Ch + (size_t)(row0 + 8) * N + col) = make_ushort2(hh_[2], hh_[3]);
            }
        }
    }
}

// ---------------- transpose + fp16: in[Rr,Cc] -> out[Cc,Rr] ----------------
__global__ void transpose_half_kernel(const float* __restrict__ in,
                                      __half* __restrict__ oh,
                                      int Rr, int Cc) {
    __shared__ float t[32][33];
    int r = blockIdx.y * 32 + threadIdx.y;
    int c = blockIdx.x * 32 + threadIdx.x;
    t[threadIdx.y][threadIdx.x] = in[(size_t)r * Cc + c];
    __syncthreads();
    int orow = blockIdx.x * 32 + threadIdx.y;
    int ocol = blockIdx.y * 32 + threadIdx.x;
    oh[(size_t)orow * Rr + ocol] = __float2half_rn(t[threadIdx.x][threadIdx.y]);
}

// ---------------- small kernels ----------------

__global__ void copy4_kernel(const float4* __restrict__ src, float4* __restrict__ dst) {
    size_t i = (size_t)blockIdx.x * blockDim.x + threadIdx.x;
    dst[i] = src[i];
}

// pass_w[p] = sigmoid( sum_i tile(reg_init,5)[i] * ms3_w[i,p] + ms3_b[p] ) — one block per p
__global__ void passw_kernel(const float* __restrict__ reg_init,
                             const float* __restrict__ W,
                             const float* __restrict__ b,
                             float* __restrict__ pw) {
    __shared__ float red[256];
    int p = blockIdx.x;
    int tid = threadIdx.x;
    float acc = 0.f;
    for (int i = tid; i < PP * RDR; i += 256)
        acc += reg_init[i % RDR] * W[i * PP + p];
    red[tid] = acc; __syncthreads();
    #pragma unroll
    for (int o = 128; o > 0; o >>= 1) { if (tid < o) red[tid] += red[tid + o]; __syncthreads(); }
    if (tid == 0) pw[p] = 1.f / (1.f + expf(-(red[0] + b[p])));
}

__global__ void qproj_kernel(const float* __restrict__ bank, int n,
                             const float* __restrict__ Wq, float* __restrict__ q) {
    int d = blockIdx.x * blockDim.x + threadIdx.x;
    if (d >= DD) return;
    float acc = 0.f;
    #pragma unroll 16
    for (int i = 0; i < n; i++)
        acc += bank[i] * Wq[(size_t)i * DD + d];
    q[d] = acc;
}

__global__ void matvec_kernel(const float* __restrict__ M,
                              const float* __restrict__ v,
                              float* __restrict__ out) {
    __shared__ float red[128];
    int r = blockIdx.x;
    int tid = threadIdx.x;
    float acc = 0.f;
    #pragma unroll
    for (int j = tid; j < DD; j += 128)
        acc += M[(size_t)r * DD + j] * v[j];
    red[tid] = acc; __syncthreads();
    for (int o = 64; o > 0; o >>= 1) {
        if (tid < o) red[tid] += red[tid + o];
        __syncthreads();
    }
    if (tid == 0) out[r] = red[0];
}

__global__ void vecmat_kernel(const float* __restrict__ v, const float* __restrict__ M,
                              const float* __restrict__ bias, const float* __restrict__ init,
                              float* __restrict__ out, int nrow, int ncol, int act) {
    int j = blockIdx.x * blockDim.x + threadIdx.x;
    if (j >= ncol) return;
    float acc = 0.f;
    #pragma unroll 16
    for (int d = 0; d < nrow; d++)
        acc += v[d] * M[(size_t)d * ncol + j];
    if (bias) acc += bias[j];
    if (init) acc += init[j];
    if (act == 1) acc = 1.f / (1.f + expf(-acc));
    out[j] = acc;
}

__global__ void ln_kernel(const float* __restrict__ in, float* __restrict__ out,
                          const float* __restrict__ gs, const float* __restrict__ gb,
                          const float* __restrict__ kq, float* __restrict__ score) {
    __shared__ float red[256];
    int t = blockIdx.x;
    int tid = threadIdx.x;
    const float* row = in + (size_t)t * DD;
    float x0 = row[tid];
    float x1 = row[tid + 256];
    red[tid] = x0 + x1; __syncthreads();
    #pragma unroll
    for (int o = 128; o > 0; o >>= 1) { if (tid < o) red[tid] += red[tid + o]; __syncthreads(); }
    float mean = red[0] * (1.0f / 512.0f);
    __syncthreads();
    float d0 = x0 - mean, d1 = x1 - mean;
    red[tid] = d0 * d0 + d1 * d1; __syncthreads();
    #pragma unroll
    for (int o = 128; o > 0; o >>= 1) { if (tid < o) red[tid] += red[tid + o]; __syncthreads(); }
    float rstd = rsqrtf(red[0] * (1.0f / 512.0f) + 1e-5f);
    __syncthreads();
    float y0 = d0 * rstd * gs[tid] + gb[tid];
    float y1 = d1 * rstd * gs[tid + 256] + gb[tid + 256];
    out[(size_t)t * DD + tid] = y0;
    out[(size_t)t * DD + tid + 256] = y1;
    if (kq) {
        red[tid] = y0 * kq[tid] + y1 * kq[tid + 256]; __syncthreads();
        #pragma unroll
        for (int o = 128; o > 0; o >>= 1) { if (tid < o) red[tid] += red[tid + o]; __syncthreads(); }
        if (tid == 0) score[t] = red[0] * 0.044194173824159216f;
    }
}

// LayerNorm emitting fp16 (for the FFN GEMM input)
__global__ void ln_fp16_kernel(const float* __restrict__ in,
                               __half* __restrict__ oh,
                               const float* __restrict__ gs, const float* __restrict__ gb) {
    __shared__ float red[256];
    int t = blockIdx.x;
    int tid = threadIdx.x;
    const float* row = in + (size_t)t * DD;
    float x0 = row[tid];
    float x1 = row[tid + 256];
    red[tid] = x0 + x1; __syncthreads();
    #pragma unroll
    for (int o = 128; o > 0; o >>= 1) { if (tid < o) red[tid] += red[tid + o]; __syncthreads(); }
    float mean = red[0] * (1.0f / 512.0f);
    __syncthreads();
    float d0 = x0 - mean, d1 = x1 - mean;
    red[tid] = d0 * d0 + d1 * d1; __syncthreads();
    #pragma unroll
    for (int o = 128; o > 0; o >>= 1) { if (tid < o) red[tid] += red[tid + o]; __syncthreads(); }
    float rstd = rsqrtf(red[0] * (1.0f / 512.0f) + 1e-5f);
    float y0 = d0 * rstd * gs[tid] + gb[tid];
    float y1 = d1 * rstd * gs[tid + 256] + gb[tid + 256];
    oh[(size_t)t * DD + tid]       = __float2half_rn(y0);
    oh[(size_t)t * DD + tid + 256] = __float2half_rn(y1);
}

__global__ void softmax_kernel(float* __restrict__ sc) {
    __shared__ float red[1024];
    int b = blockIdx.x;
    float* p = sc + (size_t)b * LL;
    int tid = threadIdx.x;
    float v0 = p[tid], v1 = p[tid + 1024];
    red[tid] = fmaxf(v0, v1); __syncthreads();
    #pragma unroll
    for (int o = 512; o > 0; o >>= 1) { if (tid < o) red[tid] = fmaxf(red[tid], red[tid + o]); __syncthreads(); }
    float mx = red[0];
    __syncthreads();
    float e0 = expf(v0 - mx), e1 = expf(v1 - mx);
    red[tid] = e0 + e1; __syncthreads();
    #pragma unroll
    for (int o = 512; o > 0; o >>= 1) { if (tid < o) red[tid] += red[tid + o]; __syncthreads(); }
    float inv = 1.f / red[0];
    p[tid] = e0 * inv;
    p[tid + 1024] = e1 * inv;
}

__global__ void wxpart_kernel(const float* __restrict__ a, const float* __restrict__ xn,
                              float* __restrict__ part) {
    int d = threadIdx.x;
    int blk = blockIdx.x;
    int row0 = blk * 64;
    float acc = 0.f;
    #pragma unroll 8
    for (int r = row0; r < row0 + 64; r++)
        acc += a[r] * xn[(size_t)r * DD + d];
    part[(size_t)blk * DD + d] = acc;
}

__global__ void colsum_part_kernel(const float* __restrict__ delta, float* __restrict__ part) {
    int d = threadIdx.x;
    int c = blockIdx.x;
    float acc = 0.f;
    #pragma unroll 8
    for (int r = c * 64; r < (c + 1) * 64; r++)
        acc += delta[(size_t)r * DD + d];
    part[(size_t)c * DD + d] = acc;
}

__global__ void part_reduce_kernel(const float* __restrict__ part, float* __restrict__ out,
                                   int nchunk, float scale) {
    int d = threadIdx.x;
    int g = blockIdx.x;
    const float* p = part + (size_t)g * nchunk * DD;
    float acc = 0.f;
    #pragma unroll 8
    for (int c = 0; c < nchunk; c++)
        acc += p[(size_t)c * DD + d];
    out[(size_t)g * DD + d] = acc * scale;
}

// residual += pw[p] * gate[d] * delta   (float4)
__global__ void resupd_kernel(float4* __restrict__ res, const float4* __restrict__ delta,
                              const float4* __restrict__ gate, const float* __restrict__ pw, int p) {
    size_t i = (size_t)blockIdx.x * blockDim.x + threadIdx.x;
    float w = pw[p];
    float4 g = gate[i & 127];
    float4 d = delta[i];
    float4 r = res[i];
    r.x += w * g.x * d.x;
    r.y += w * g.y * d.y;
    r.z += w * g.z * d.z;
    r.w += w * g.w * d.w;
    res[i] = r;
}

__global__ void wg_kernel(const float* __restrict__ summary, const float* __restrict__ W,
                          const float* __restrict__ b, float* __restrict__ wg) {
    __shared__ float red[512];
    int tid = threadIdx.x;
    for (int r = 0; r < RR; r++) {
        red[tid] = summary[tid] * W[(size_t)r * DD + tid];
        __syncthreads();
        #pragma unroll
        for (int o = 256; o > 0; o >>= 1) { if (tid < o) red[tid] += red[tid + o]; __syncthreads(); }
        if (tid == 0) wg[r] = 1.f / (1.f + expf(-(red[0] + b[r])));
        __syncthreads();
    }
}

__global__ void regsupd_kernel(const float* __restrict__ summary, const float* __restrict__ Wp,
                               const float* __restrict__ wg, float* __restrict__ regs) {
    int r = blockIdx.x;
    int k = threadIdx.x;
    const float* W = Wp + (size_t)r * DD * DRR;
    float acc = 0.f;
    #pragma unroll 16
    for (int d = 0; d < DD; d++)
        acc += summary[d] * W[(size_t)d * DRR + k];
    regs[r * DRR + k] += wg[r] * acc;
}

__global__ void bankcopy_kernel(const float* __restrict__ regs, float* __restrict__ banks, int p) {
    int j = threadIdx.x;
    banks[p * RDR + j] = regs[j];
}

// residual[b,l,:] += mo[b,:]   (float4)
__global__ void resmo_kernel(float4* __restrict__ res, const float4* __restrict__ mo) {
    size_t i = (size_t)blockIdx.x * blockDim.x + threadIdx.x;
    int b = (int)(i >> 18);               // (2048*512/4) = 1<<18 float4 per batch
    float4 m = mo[(b << 7) + (int)(i & 127)];
    float4 r = res[i];
    r.x += m.x; r.y += m.y; r.z += m.z; r.w += m.w;
    res[i] = r;
}

// ---------------- host orchestration ----------------

extern "C" void kernel_launch(void* const* d_in, const int* in_sizes, int n_in,
                              void* d_out, int out_size) {
    const float* x        = (const float*)d_in[0];
    const float* reg_init = (const float*)d_in[1];
    const float* ffn_ln_s = (const float*)d_in[2];
    const float* ffn_ln_b = (const float*)d_in[3];
    const float* ffn_w1   = (const float*)d_in[4];
    const float* ffn_b1   = (const float*)d_in[5];
    const float* ffn_w2   = (const float*)d_in[6];
    const float* ffn_b2   = (const float*)d_in[7];
    const float* gate_w   = (const float*)d_in[8];
    const float* gate_b   = (const float*)d_in[9];
    const float* wproj_w  = (const float*)d_in[10];
    const float* wgate_w  = (const float*)d_in[11];
    const float* wgate_b  = (const float*)d_in[12];
    const float* s4_q     = (const float*)d_in[13];
    const float* s4_k     = (const float*)d_in[14];
    const float* s4_v     = (const float*)d_in[15];
    const float* s4_sum   = (const float*)d_in[16];
    const float* s4_ln_s  = (const float*)d_in[17];
    const float* s4_ln_b  = (const float*)d_in[18];
    const float* ms3_w    = (const float*)d_in[19];
    const float* ms3_b    = (const float*)d_in[20];
    const float* m4_q     = (const float*)d_in[21];
    const float* m4_k     = (const float*)d_in[22];
    const float* m4_v     = (const float*)d_in[23];
    const float* m4_out   = (const float*)d_in[24];
    const float* m4_ln_s  = (const float*)d_in[25];
    const float* m4_ln_b  = (const float*)d_in[26];
    const float* out_ln_s = (const float*)d_in[27];
    const float* out_ln_b = (const float*)d_in[28];

    float *res, *xn, *delta, *sc, *part, *q, *kq, *wxm, *summ, *regs, *gate, *wg;
    float *banks, *pw, *wxb, *ms1, *mo;
    __half *xnh, *hh, *w1th, *w2th;
    cudaGetSymbolAddress((void**)&res,   g_res);
    cudaGetSymbolAddress((void**)&xn,    g_xn);
    cudaGetSymbolAddress((void**)&delta, g_delta);
    cudaGetSymbolAddress((void**)&sc,    g_sc);
    cudaGetSymbolAddress((void**)&part,  g_part);
    cudaGetSymbolAddress((void**)&q,     g_q);
    cudaGetSymbolAddress((void**)&kq,    g_kq);
    cudaGetSymbolAddress((void**)&wxm,   g_wxm);
    cudaGetSymbolAddress((void**)&summ,  g_summ);
    cudaGetSymbolAddress((void**)&regs,  g_regs);
    cudaGetSymbolAddress((void**)&gate,  g_gate);
    cudaGetSymbolAddress((void**)&wg,    g_wg);
    cudaGetSymbolAddress((void**)&banks, g_banks);
    cudaGetSymbolAddress((void**)&pw,    g_pw);
    cudaGetSymbolAddress((void**)&wxb,   g_wxb);
    cudaGetSymbolAddress((void**)&ms1,   g_ms1);
    cudaGetSymbolAddress((void**)&mo,    g_mo);
    cudaGetSymbolAddress((void**)&xnh,   g_xnh);
    cudaGetSymbolAddress((void**)&hh,    g_hh);
    cudaGetSymbolAddress((void**)&w1th,  g_w1th);
    cudaGetSymbolAddress((void**)&w2th,  g_w2th);

    const int ELEM = NTOK * DD;

    // dynamic smem opt-in (idempotent)
    cudaFuncSetAttribute(mmagemm_kernel<0>, cudaFuncAttributeMaxDynamicSharedMemorySize, 2 * STAGE_BYTES);
    cudaFuncSetAttribute(mmagemm_kernel<1>, cudaFuncAttributeMaxDynamicSharedMemorySize, 2 * STAGE_BYTES);

    // weight transpose -> fp16 (per replay; cheap and deterministic)
    for (int ph = 0; ph < PHH; ph++) {
        dim3 blk(32, 32);
        dim3 g1(FF / 32, DD / 32);   // w1 [D,F] -> [F,D]
        transpose_half_kernel<<<g1, blk>>>(ffn_w1 + (size_t)ph * DD * FF,
                                           w1th + (size_t)ph * FF * DD, DD, FF);
        dim3 g2(DD / 32, FF / 32);   // w2 [F,D] -> [D,F]
        transpose_half_kernel<<<g2, blk>>>(ffn_w2 + (size_t)ph * FF * DD,
                                           w2th + (size_t)ph * DD * FF, FF, DD);
    }

    copy4_kernel<<<ELEM / 4 / 256, 256>>>((const float4*)x, (float4*)res);
    passw_kernel<<<PP, 256>>>(reg_init, ms3_w, ms3_b, pw);

    for (int p = 0; p < PP; p++) {
        // ---- S4 read (collapsed attention) ----
        qproj_kernel<<<2, 256>>>(banks, p * RDR, s4_q, q);
        matvec_kernel<<<512, 128>>>(s4_k, q, kq);
        ln_kernel<<<NTOK, 256>>>(res, xn, s4_ln_s, s4_ln_b, kq, sc);
        softmax_kernel<<<BB, 1024>>>(sc);
        wxpart_kernel<<<128, 512>>>(sc, xn, part);
        part_reduce_kernel<<<1, 512>>>(part, wxm, 128, 1.0f / BB);
        vecmat_kernel<<<2, 256>>>(wxm, s4_v, nullptr, nullptr, summ, DD, DD, 0);
        vecmat_kernel<<<3, 256>>>(summ, s4_sum, nullptr, reg_init, regs, DD, RDR, 0);

        for (int ph = 0; ph < PHH; ph++) {
            const int pp = p * PHH + ph;
            // FFN: LN -> fp16 GEMM (gelu, fp16 out) -> fp16 GEMM (fp32 out)
            ln_fp16_kernel<<<NTOK, 256>>>(res, xnh,
                                          ffn_ln_s + (size_t)ph * DD,
                                          ffn_ln_b + (size_t)ph * DD);
            {
                dim3 grid(FF / 128, NTOK / 128);
                mmagemm_kernel<1><<<grid, 256, 2 * STAGE_BYTES>>>(
                    xnh, w1th + (size_t)ph * FF * DD,
                    ffn_b1 + (size_t)ph * FF, nullptr, hh, NTOK, FF, DD);
            }
            {
                dim3 grid(DD / 128, NTOK / 128);
                mmagemm_kernel<0><<<grid, 256, 2 * STAGE_BYTES>>>(
                    hh, w2th + (size_t)ph * DD * FF,
                    ffn_b2 + (size_t)ph * DD, delta, nullptr, NTOK, DD, FF);
            }
            // summary = mean over tokens of delta
            colsum_part_kernel<<<128, 512>>>(delta, part);
            part_reduce_kernel<<<1, 512>>>(part, regs + RDR, 128, 1.0f / (float)NTOK);
            // gate = sigmoid([regs|summary] @ gate_w + gate_b)
            vecmat_kernel<<<2, 256>>>(regs, gate_w + (size_t)pp * (RDR + DD) * DD,
                                      gate_b + (size_t)pp * DD, nullptr, gate,
                                      RDR + DD, DD, 1);
            resupd_kernel<<<ELEM / 4 / 256, 256>>>((float4*)res, (const float4*)delta,
                                                   (const float4*)gate, pw, p);
            // register update
            wg_kernel<<<1, 512>>>(regs + RDR, wgate_w + (size_t)pp * RR * DD,
                                  wgate_b + (size_t)pp * RR, wg);
            regsupd_kernel<<<RR, DRR>>>(regs + RDR, wproj_w + (size_t)pp * RR * DD * DRR,
                                        wg, regs);
        }
        bankcopy_kernel<<<1, RDR>>>(regs, banks, p);
    }

    // ---- MetaS4 ----
    qproj_kernel<<<2, 256>>>(banks, PP * RDR, m4_q, q);
    matvec_kernel<<<512, 128>>>(m4_k, q, kq);
    ln_kernel<<<NTOK, 256>>>(res, xn, m4_ln_s, m4_ln_b, kq, sc);
    softmax_kernel<<<BB, 1024>>>(sc);
    wxpart_kernel<<<128, 512>>>(sc, xn, part);
    part_reduce_kernel<<<BB, 512>>>(part, wxb, 32, 1.0f);
    for (int b = 0; b < BB; b++) {
        vecmat_kernel<<<2, 256>>>(wxb + (size_t)b * DD, m4_v, nullptr, nullptr,
                                  ms1 + (size_t)b * DD, DD, DD, 0);
        vecmat_kernel<<<2, 256>>>(ms1 + (size_t)b * DD, m4_out, nullptr, nullptr,
                                  mo + (size_t)b * DD, DD, DD, 0);
    }
    resmo_kernel<<<ELEM / 4 / 256, 256>>>((float4*)res, (const float4*)mo);

    // ---- final LayerNorm -> output ----
    ln_kernel<<<NTOK, 256>>>(res, (float*)d_out, out_ln_s, out_ln_b, nullptr, nullptr);
}

// round 7
// speedup vs baseline: 5.6491x; 2.1978x over previous
#include <cuda_runtime.h>
#include <cuda_fp16.h>
#include <math.h>
#include <stdint.h>

// ---------------- problem constants ----------------
#define BB 4
#define LL 2048
#define DD 512
#define DRR 256
#define RR 3
#define PP 5
#define PHH 3
#define FF 1536
#define NTOK (BB*LL)            // 8192
#define RDR (RR*DRR)            // 768

// ---------------- device scratch ----------------
__device__ __align__(256) float g_res[NTOK*DD];
__device__ __align__(256) float g_xn[NTOK*DD];
__device__ __align__(256) float g_delta[NTOK*DD];
__device__ __align__(256) float g_sc[NTOK];
__device__ __align__(256) float g_part[128*DD];
__device__ __align__(256) float g_q[DD];
__device__ __align__(256) float g_kq[DD];
__device__ __align__(256) float g_wxm[DD];
__device__ __align__(256) float g_summ[DD];
__device__ __align__(256) float g_regs[RDR + DD];   // gin = [regs | summary]
__device__ __align__(256) float g_gate[DD];
__device__ __align__(256) float g_banks[PP*RDR];
__device__ __align__(256) float g_pw[16];
__device__ __align__(256) float g_wxb[BB*DD];
__device__ __align__(256) float g_ms1[BB*DD];
__device__ __align__(256) float g_mo[BB*DD];

__device__ __align__(256) __half g_xnh[NTOK*DD];
__device__ __align__(256) __half g_hh[NTOK*FF];
__device__ __align__(256) __half g_w1th[PHH*FF*DD];
__device__ __align__(256) __half g_w2th[PHH*DD*FF];

// ---------------- PTX helpers ----------------
__device__ __forceinline__ uint32_t smem_u32(const void* p) {
    return (uint32_t)__cvta_generic_to_shared(p);
}
__device__ __forceinline__ void cpasync16(uint32_t dst, const void* src) {
    asm volatile("cp.async.cg.shared.global [%0], [%1], 16;" :: "r"(dst), "l"(src) : "memory");
}
__device__ __forceinline__ void cp_commit() {
    asm volatile("cp.async.commit_group;" ::: "memory");
}
__device__ __forceinline__ void cp_wait1() {
    asm volatile("cp.async.wait_group 1;" ::: "memory");
}
__device__ __forceinline__ void ldsm4(uint32_t* r, uint32_t addr) {
    asm volatile("ldmatrix.sync.aligned.m8n8.x4.shared.b16 {%0,%1,%2,%3}, [%4];"
                 : "=r"(r[0]), "=r"(r[1]), "=r"(r[2]), "=r"(r[3]) : "r"(addr));
}
__device__ __forceinline__ void mma16816(float* c, const uint32_t* a, uint32_t b0, uint32_t b1) {
    asm volatile(
        "mma.sync.aligned.m16n8k16.row.col.f32.f16.f16.f32 "
        "{%0,%1,%2,%3}, {%4,%5,%6,%7}, {%8,%9}, {%0,%1,%2,%3};"
        : "+f"(c[0]), "+f"(c[1]), "+f"(c[2]), "+f"(c[3])
        : "r"(a[0]), "r"(a[1]), "r"(a[2]), "r"(a[3]), "r"(b0), "r"(b1));
}

// ---------------- fp16 GEMM via mma.sync ----------------
// C[M,N] = A[M,K] @ B^T. fp32 accumulate.
// OUTMODE 0: Cf = acc + bias; also emits per-CTA column partial sums of acc
//            (WITHOUT bias) into part[by*512 + col].
// OUTMODE 1: Ch = fp16(gelu(acc+bias)).
// CTA tile 128x128, 256 thr (8 warps: 4m x 2n, warp tile 32x64), kchunk 64,
// 2-stage cp.async pipeline (64KB dynamic smem), XOR-swizzled K-major smem.

#define STAGE_BYTES 32768           // A 16KB + B 16KB

template <int OUTMODE>
__global__ void __launch_bounds__(256, 2)
mmagemm_kernel(const __half* __restrict__ Ah, const __half* __restrict__ Bh,
               const float* __restrict__ bias,
               float* __restrict__ Cf, __half* __restrict__ Ch,
               float* __restrict__ part,
               int M, int N, int K) {
    extern __shared__ __align__(128) unsigned char smem[];   // 2 * 32KB

    const int tid  = threadIdx.x;
    const int wid  = tid >> 5;
    const int lane = tid & 31;
    const int n0 = blockIdx.x * 128;
    const int m0 = blockIdx.y * 128;

    const int NIT = K >> 6;             // k64 chunks

    const uint32_t smem_base = smem_u32(smem);

    int lrowA[4]; int lcA[4]; uint32_t ldst[4];
    #pragma unroll
    for (int u = 0; u < 4; u++) {
        int s = tid + u * 256;
        int row = s >> 3, c = s & 7;
        lrowA[u] = row; lcA[u] = c;
        ldst[u] = (uint32_t)(row * 128 + ((c ^ (row & 7)) << 4));
    }

    auto prefetch = [&](int it) {
        const int k0 = it << 6;
        const uint32_t st = smem_base + (uint32_t)(it & 1) * STAGE_BYTES;
        #pragma unroll
        for (int u = 0; u < 4; u++)
            cpasync16(st + ldst[u], Ah + (size_t)(m0 + lrowA[u]) * K + k0 + lcA[u] * 8);
        #pragma unroll
        for (int u = 0; u < 4; u++)
            cpasync16(st + 16384 + ldst[u], Bh + (size_t)(n0 + lrowA[u]) * K + k0 + lcA[u] * 8);
        cp_commit();
    };

    float acc[2][8][4];
    #pragma unroll
    for (int i = 0; i < 2; i++)
        #pragma unroll
        for (int j = 0; j < 8; j++)
            #pragma unroll
            for (int t = 0; t < 4; t++) acc[i][j][t] = 0.f;

    const int wm = (wid & 3) * 32;
    const int wn = (wid >> 2) * 64;
    const int lrow = lane & 15;
    const int lseg = lane >> 4;

    prefetch(0);
    if (NIT > 1) prefetch(1);

    #pragma unroll 1
    for (int it = 0; it < NIT; it++) {
        cp_wait1();
        __syncthreads();

        const uint32_t st = smem_base + (uint32_t)(it & 1) * STAGE_BYTES;
        #pragma unroll
        for (int kk = 0; kk < 4; kk++) {
            uint32_t af[2][4];
            #pragma unroll
            for (int i = 0; i < 2; i++) {
                int row = wm + i * 16 + lrow;
                int seg = kk * 2 + lseg;
                ldsm4(af[i], st + (uint32_t)(row * 128 + (((seg ^ (row & 7))) << 4)));
            }
            uint32_t bf[4][4];
            #pragma unroll
            for (int g = 0; g < 4; g++) {
                int row = wn + g * 16 + lrow;
                int seg = kk * 2 + lseg;
                ldsm4(bf[g], st + 16384u + (uint32_t)(row * 128 + (((seg ^ (row & 7))) << 4)));
            }
            #pragma unroll
            for (int i = 0; i < 2; i++)
                #pragma unroll
                for (int j = 0; j < 8; j++) {
                    int g = j >> 1, w = j & 1;
                    mma16816(acc[i][j], af[i], bf[g][w], bf[g][w + 2]);
                }
        }
        __syncthreads();
        if (it + 2 < NIT) prefetch(it + 2);
    }

    // ---- epilogue ----
    const int l4 = lane >> 2;
    const int l2 = (lane & 3) * 2;

    if (OUTMODE == 0) {
        // per-CTA column partial sums of acc (no bias), deterministic order
        float cs0[8], cs1[8];
        #pragma unroll
        for (int j = 0; j < 8; j++) {
            cs0[j] = acc[0][j][0] + acc[0][j][2] + acc[1][j][0] + acc[1][j][2];
            cs1[j] = acc[0][j][1] + acc[0][j][3] + acc[1][j][1] + acc[1][j][3];
            #pragma unroll
            for (int off = 4; off <= 16; off <<= 1) {
                cs0[j] += __shfl_xor_sync(0xffffffffu, cs0[j], off);
                cs1[j] += __shfl_xor_sync(0xffffffffu, cs1[j], off);
            }
        }
        float* cs = (float*)smem;   // stage data dead after final mainloop sync
        if (lane < 4) {
            #pragma unroll
            for (int j = 0; j < 8; j++) {
                cs[wid * 64 + j * 8 + lane * 2 + 0] = cs0[j];
                cs[wid * 64 + j * 8 + lane * 2 + 1] = cs1[j];
            }
        }
        __syncthreads();
        if (tid < 128) {
            int ng = tid >> 6, cw = tid & 63;
            float s = cs[(ng * 4 + 0) * 64 + cw] + cs[(ng * 4 + 1) * 64 + cw]
                    + cs[(ng * 4 + 2) * 64 + cw] + cs[(ng * 4 + 3) * 64 + cw];
            part[(size_t)blockIdx.y * 512 + n0 + ng * 64 + cw] = s;
        }
    }

    #pragma unroll
    for (int i = 0; i < 2; i++) {
        #pragma unroll
        for (int j = 0; j < 8; j++) {
            const int col  = n0 + wn + j * 8 + l2;
            const int row0 = m0 + wm + i * 16 + l4;
            const float b0v = bias[col];
            const float b1v = bias[col + 1];
            float v00 = acc[i][j][0] + b0v, v01 = acc[i][j][1] + b1v;
            float v10 = acc[i][j][2] + b0v, v11 = acc[i][j][3] + b1v;
            if (OUTMODE == 0) {
                *(float2*)(Cf + (size_t)row0 * N + col)       = make_float2(v00, v01);
                *(float2*)(Cf + (size_t)(row0 + 8) * N + col) = make_float2(v10, v11);
            } else {
                float vv[4] = {v00, v01, v10, v11};
                unsigned short hh_[4];
                #pragma unroll
                for (int t = 0; t < 4; t++) {
                    float v = vv[t];
                    v = 0.5f * v * (1.0f + erff(v * 0.70710678118654752f));
                    hh_[t] = __half_as_ushort(__float2half_rn(v));
                }
                *(ushort2*)((unsigned short*)Ch + (size_t)row0 * N + col)       = make_ushort2(hh_[0], hh_[1]);
                *(ushort2*)((unsigned short*)Ch + (size_t)(row0 + 8) * N + col) = make_ushort2(hh_[2], hh_[3]);
            }
        }
    }
}

// ---------------- fused residual-update + LayerNorm ----------------
// INMODE: 0 none, 1 res += pw[p]*gate*delta (writes res), 2 r = res + mo[b] (no writeback)
// EMIT_XN: xn = LN(r; sA,bA); if kq: score[t] = dot(xn,kq)*D^-0.5
// EMIT_XNH: xnh = fp16(LN(r; sB,bB))
template <int INMODE, int EMIT_XN, int EMIT_XNH>
__global__ void fused_ln_kernel(float* __restrict__ res, const float* __restrict__ delta,
                                const float* __restrict__ gate, const float* __restrict__ pw, int p,
                                const float* __restrict__ mo,
                                const float* __restrict__ sA, const float* __restrict__ bA,
                                const float* __restrict__ kq, float* __restrict__ score,
                                float* __restrict__ xn,
                                const float* __restrict__ sB, const float* __restrict__ bB,
                                __half* __restrict__ xnh) {
    __shared__ float red[256];
    int t = blockIdx.x;
    int tid = threadIdx.x;
    size_t o0 = (size_t)t * DD + tid, o1 = o0 + 256;
    float r0 = res[o0], r1 = res[o1];
    if (INMODE == 1) {
        float w = pw[p];
        r0 += w * gate[tid]       * delta[o0];
        r1 += w * gate[tid + 256] * delta[o1];
        res[o0] = r0; res[o1] = r1;
    } else if (INMODE == 2) {
        int b = t >> 11;
        r0 += mo[(b << 9) + tid];
        r1 += mo[(b << 9) + tid + 256];
    }
    red[tid] = r0 + r1; __syncthreads();
    #pragma unroll
    for (int o = 128; o > 0; o >>= 1) { if (tid < o) red[tid] += red[tid + o]; __syncthreads(); }
    float mean = red[0] * (1.0f / 512.0f);
    __syncthreads();
    float d0 = r0 - mean, d1 = r1 - mean;
    red[tid] = d0 * d0 + d1 * d1; __syncthreads();
    #pragma unroll
    for (int o = 128; o > 0; o >>= 1) { if (tid < o) red[tid] += red[tid + o]; __syncthreads(); }
    float rstd = rsqrtf(red[0] * (1.0f / 512.0f) + 1e-5f);
    __syncthreads();
    if (EMIT_XN) {
        float y0 = d0 * rstd * sA[tid] + bA[tid];
        float y1 = d1 * rstd * sA[tid + 256] + bA[tid + 256];
        xn[o0] = y0; xn[o1] = y1;
        if (kq) {
            red[tid] = y0 * kq[tid] + y1 * kq[tid + 256]; __syncthreads();
            #pragma unroll
            for (int o = 128; o > 0; o >>= 1) { if (tid < o) red[tid] += red[tid + o]; __syncthreads(); }
            if (tid == 0) score[t] = red[0] * 0.044194173824159216f;
        }
    }
    if (EMIT_XNH) {
        float z0 = d0 * rstd * sB[tid] + bB[tid];
        float z1 = d1 * rstd * sB[tid + 256] + bB[tid + 256];
        xnh[o0] = __float2half_rn(z0);
        xnh[o1] = __float2half_rn(z1);
    }
}

// ---------------- k-split vec @ mat: out[j] = act(init + v@M + bias) ----------------
// grid = ncol/64, block 512 = 64 cols x 8 k-slices. nrow % 8 == 0.
__global__ void vecmat_split_kernel(const float* __restrict__ v, const float* __restrict__ M,
                                    const float* __restrict__ bias, const float* __restrict__ init,
                                    float* __restrict__ out, int nrow, int ncol, int act) {
    __shared__ float red[512];
    int tid = threadIdx.x;
    int j = blockIdx.x * 64 + (tid & 63);
    int s = tid >> 6;                   // slice 0..7
    int sl = nrow >> 3;
    float acc = 0.f;
    #pragma unroll 16
    for (int d = s * sl; d < (s + 1) * sl; d++)
        acc += v[d] * M[(size_t)d * ncol + j];
    red[tid] = acc; __syncthreads();
    if (tid < 64) {
        float a = 0.f;
        #pragma unroll
        for (int k = 0; k < 8; k++) a += red[k * 64 + tid];
        if (bias) a += bias[j];
        if (init) a += init[j];
        if (act == 1) a = 1.f / (1.f + expf(-a));
        out[j] = a;
    }
}

// ---------------- other small kernels ----------------

__global__ void transpose_half_kernel(const float* __restrict__ in,
                                      __half* __restrict__ oh,
                                      int Rr, int Cc) {
    __shared__ float t[32][33];
    int r = blockIdx.y * 32 + threadIdx.y;
    int c = blockIdx.x * 32 + threadIdx.x;
    t[threadIdx.y][threadIdx.x] = in[(size_t)r * Cc + c];
    __syncthreads();
    int orow = blockIdx.x * 32 + threadIdx.y;
    int ocol = blockIdx.y * 32 + threadIdx.x;
    oh[(size_t)orow * Rr + ocol] = __float2half_rn(t[threadIdx.x][threadIdx.y]);
}

__global__ void copy4_kernel(const float4* __restrict__ src, float4* __restrict__ dst) {
    size_t i = (size_t)blockIdx.x * blockDim.x + threadIdx.x;
    dst[i] = src[i];
}

__global__ void passw_kernel(const float* __restrict__ reg_init,
                             const float* __restrict__ W,
                             const float* __restrict__ b,
                             float* __restrict__ pw) {
    __shared__ float red[256];
    int p = blockIdx.x;
    int tid = threadIdx.x;
    float acc = 0.f;
    for (int i = tid; i < PP * RDR; i += 256)
        acc += reg_init[i % RDR] * W[i * PP + p];
    red[tid] = acc; __syncthreads();
    #pragma unroll
    for (int o = 128; o > 0; o >>= 1) { if (tid < o) red[tid] += red[tid + o]; __syncthreads(); }
    if (tid == 0) pw[p] = 1.f / (1.f + expf(-(red[0] + b[p])));
}

__global__ void matvec_kernel(const float* __restrict__ M,
                              const float* __restrict__ v,
                              float* __restrict__ out) {
    __shared__ float red[128];
    int r = blockIdx.x;
    int tid = threadIdx.x;
    float acc = 0.f;
    #pragma unroll
    for (int j = tid; j < DD; j += 128)
        acc += M[(size_t)r * DD + j] * v[j];
    red[tid] = acc; __syncthreads();
    for (int o = 64; o > 0; o >>= 1) {
        if (tid < o) red[tid] += red[tid + o];
        __syncthreads();
    }
    if (tid == 0) out[r] = red[0];
}

__global__ void softmax_kernel(float* __restrict__ sc) {
    __shared__ float red[1024];
    int b = blockIdx.x;
    float* p = sc + (size_t)b * LL;
    int tid = threadIdx.x;
    float v0 = p[tid], v1 = p[tid + 1024];
    red[tid] = fmaxf(v0, v1); __syncthreads();
    #pragma unroll
    for (int o = 512; o > 0; o >>= 1) { if (tid < o) red[tid] = fmaxf(red[tid], red[tid + o]); __syncthreads(); }
    float mx = red[0];
    __syncthreads();
    float e0 = expf(v0 - mx), e1 = expf(v1 - mx);
    red[tid] = e0 + e1; __syncthreads();
    #pragma unroll
    for (int o = 512; o > 0; o >>= 1) { if (tid < o) red[tid] += red[tid + o]; __syncthreads(); }
    float inv = 1.f / red[0];
    p[tid] = e0 * inv;
    p[tid + 1024] = e1 * inv;
}

__global__ void wxpart_kernel(const float* __restrict__ a, const float* __restrict__ xn,
                              float* __restrict__ part) {
    int d = threadIdx.x;
    int blk = blockIdx.x;
    int row0 = blk * 64;
    float acc = 0.f;
    #pragma unroll 8
    for (int r = row0; r < row0 + 64; r++)
        acc += a[r] * xn[(size_t)r * DD + d];
    part[(size_t)blk * DD + d] = acc;
}

// out[g*512+d] = scale * sum_c part[(g*nchunk+c)*512+d]  (+ bias[d] if given)
__global__ void part_reduce_kernel(const float* __restrict__ part, float* __restrict__ out,
                                   int nchunk, float scale, const float* __restrict__ bias) {
    int d = threadIdx.x;
    int g = blockIdx.x;
    const float* p = part + (size_t)g * nchunk * DD;
    float acc = 0.f;
    #pragma unroll 8
    for (int c = 0; c < nchunk; c++)
        acc += p[(size_t)c * DD + d];
    acc *= scale;
    if (bias) acc += bias[d];
    out[(size_t)g * DD + d] = acc;
}

// wg[r] = sigmoid(summary . Wg[r] + bg[r]); regs[r,k] += wg[r] * (summary @ Wp[r])[k]
__global__ void regsupd_kernel(const float* __restrict__ summary, const float* __restrict__ Wp,
                               const float* __restrict__ Wg, const float* __restrict__ bg,
                               float* __restrict__ regs) {
    __shared__ float red[512];
    __shared__ float shw;
    int r = blockIdx.x;
    int tid = threadIdx.x;
    red[tid] = summary[tid] * Wg[(size_t)r * DD + tid];
    __syncthreads();
    #pragma unroll
    for (int o = 256; o > 0; o >>= 1) { if (tid < o) red[tid] += red[tid + o]; __syncthreads(); }
    if (tid == 0) shw = 1.f / (1.f + expf(-(red[0] + bg[r])));
    __syncthreads();
    int k = tid & 255, s = tid >> 8;        // 2 k-slices of 256
    const float* W = Wp + (size_t)r * DD * DRR;
    float acc = 0.f;
    #pragma unroll 16
    for (int d = s * 256; d < (s + 1) * 256; d++)
        acc += summary[d] * W[(size_t)d * DRR + k];
    red[tid] = acc; __syncthreads();
    if (tid < 256)
        regs[r * DRR + k] += shw * (red[k] + red[k + 256]);
}

__global__ void bankcopy_kernel(const float* __restrict__ regs, float* __restrict__ banks, int p) {
    int j = threadIdx.x;
    banks[p * RDR + j] = regs[j];
}

// ---------------- host orchestration ----------------

extern "C" void kernel_launch(void* const* d_in, const int* in_sizes, int n_in,
                              void* d_out, int out_size) {
    const float* x        = (const float*)d_in[0];
    const float* reg_init = (const float*)d_in[1];
    const float* ffn_ln_s = (const float*)d_in[2];
    const float* ffn_ln_b = (const float*)d_in[3];
    const float* ffn_w1   = (const float*)d_in[4];
    const float* ffn_b1   = (const float*)d_in[5];
    const float* ffn_w2   = (const float*)d_in[6];
    const float* ffn_b2   = (const float*)d_in[7];
    const float* gate_w   = (const float*)d_in[8];
    const float* gate_b   = (const float*)d_in[9];
    const float* wproj_w  = (const float*)d_in[10];
    const float* wgate_w  = (const float*)d_in[11];
    const float* wgate_b  = (const float*)d_in[12];
    const float* s4_q     = (const float*)d_in[13];
    const float* s4_k     = (const float*)d_in[14];
    const float* s4_v     = (const float*)d_in[15];
    const float* s4_sum   = (const float*)d_in[16];
    const float* s4_ln_s  = (const float*)d_in[17];
    const float* s4_ln_b  = (const float*)d_in[18];
    const float* ms3_w    = (const float*)d_in[19];
    const float* ms3_b    = (const float*)d_in[20];
    const float* m4_q     = (const float*)d_in[21];
    const float* m4_k     = (const float*)d_in[22];
    const float* m4_v     = (const float*)d_in[23];
    const float* m4_out   = (const float*)d_in[24];
    const float* m4_ln_s  = (const float*)d_in[25];
    const float* m4_ln_b  = (const float*)d_in[26];
    const float* out_ln_s = (const float*)d_in[27];
    const float* out_ln_b = (const float*)d_in[28];

    float *res, *xn, *delta, *sc, *part, *q, *kq, *wxm, *summ, *regs, *gate;
    float *banks, *pw, *wxb, *ms1, *mo;
    __half *xnh, *hh, *w1th, *w2th;
    cudaGetSymbolAddress((void**)&res,   g_res);
    cudaGetSymbolAddress((void**)&xn,    g_xn);
    cudaGetSymbolAddress((void**)&delta, g_delta);
    cudaGetSymbolAddress((void**)&sc,    g_sc);
    cudaGetSymbolAddress((void**)&part,  g_part);
    cudaGetSymbolAddress((void**)&q,     g_q);
    cudaGetSymbolAddress((void**)&kq,    g_kq);
    cudaGetSymbolAddress((void**)&wxm,   g_wxm);
    cudaGetSymbolAddress((void**)&summ,  g_summ);
    cudaGetSymbolAddress((void**)&regs,  g_regs);
    cudaGetSymbolAddress((void**)&gate,  g_gate);
    cudaGetSymbolAddress((void**)&banks, g_banks);
    cudaGetSymbolAddress((void**)&pw,    g_pw);
    cudaGetSymbolAddress((void**)&wxb,   g_wxb);
    cudaGetSymbolAddress((void**)&ms1,   g_ms1);
    cudaGetSymbolAddress((void**)&mo,    g_mo);
    cudaGetSymbolAddress((void**)&xnh,   g_xnh);
    cudaGetSymbolAddress((void**)&hh,    g_hh);
    cudaGetSymbolAddress((void**)&w1th,  g_w1th);
    cudaGetSymbolAddress((void**)&w2th,  g_w2th);

    const int ELEM = NTOK * DD;

    cudaFuncSetAttribute(mmagemm_kernel<0>, cudaFuncAttributeMaxDynamicSharedMemorySize, 2 * STAGE_BYTES);
    cudaFuncSetAttribute(mmagemm_kernel<1>, cudaFuncAttributeMaxDynamicSharedMemorySize, 2 * STAGE_BYTES);

    // weight transpose -> fp16
    for (int ph = 0; ph < PHH; ph++) {
        dim3 blk(32, 32);
        dim3 g1(FF / 32, DD / 32);
        transpose_half_kernel<<<g1, blk>>>(ffn_w1 + (size_t)ph * DD * FF,
                                           w1th + (size_t)ph * FF * DD, DD, FF);
        dim3 g2(DD / 32, FF / 32);
        transpose_half_kernel<<<g2, blk>>>(ffn_w2 + (size_t)ph * FF * DD,
                                           w2th + (size_t)ph * DD * FF, FF, DD);
    }

    copy4_kernel<<<ELEM / 4 / 256, 256>>>((const float4*)x, (float4*)res);
    passw_kernel<<<PP, 256>>>(reg_init, ms3_w, ms3_b, pw);

    // p=0 S4 prep: q=0 (no banks), kq, then fused LN emitting xn+score and xnh(ph0)
    vecmat_split_kernel<<<8, 512>>>(banks, s4_q, nullptr, nullptr, q, 0, DD, 0);
    matvec_kernel<<<512, 128>>>(s4_k, q, kq);
    fused_ln_kernel<0,1,1><<<NTOK, 256>>>(res, nullptr, nullptr, nullptr, 0, nullptr,
                                          s4_ln_s, s4_ln_b, kq, sc, xn,
                                          ffn_ln_s, ffn_ln_b, xnh);

    for (int p = 0; p < PP; p++) {
        // ---- S4 read (collapsed attention; xn+sc already ready) ----
        softmax_kernel<<<BB, 1024>>>(sc);
        wxpart_kernel<<<128, 512>>>(sc, xn, part);
        part_reduce_kernel<<<1, 512>>>(part, wxm, 128, 1.0f / BB, nullptr);
        vecmat_split_kernel<<<8, 512>>>(wxm, s4_v, nullptr, nullptr, summ, DD, DD, 0);
        vecmat_split_kernel<<<12, 512>>>(summ, s4_sum, nullptr, reg_init, regs, DD, RDR, 0);

        for (int ph = 0; ph < PHH; ph++) {
            const int pp = p * PHH + ph;
            {
                dim3 grid(FF / 128, NTOK / 128);
                mmagemm_kernel<1><<<grid, 256, 2 * STAGE_BYTES>>>(
                    xnh, w1th + (size_t)ph * FF * DD,
                    ffn_b1 + (size_t)ph * FF, nullptr, hh, nullptr, NTOK, FF, DD);
            }
            {
                dim3 grid(DD / 128, NTOK / 128);
                mmagemm_kernel<0><<<grid, 256, 2 * STAGE_BYTES>>>(
                    hh, w2th + (size_t)ph * DD * FF,
                    ffn_b2 + (size_t)ph * DD, delta, nullptr, part, NTOK, DD, FF);
            }
            // summary = mean(delta) = mean(acc) + b2 ; stored at regs+RDR (gin layout)
            part_reduce_kernel<<<1, 512>>>(part, regs + RDR, 64, 1.0f / (float)NTOK,
                                           ffn_b2 + (size_t)ph * DD);
            // gate = sigmoid([regs|summary] @ gate_w + gate_b)  (before regs update)
            vecmat_split_kernel<<<8, 512>>>(regs, gate_w + (size_t)pp * (RDR + DD) * DD,
                                            gate_b + (size_t)pp * DD, nullptr, gate,
                                            RDR + DD, DD, 1);
            // register update (wg fused)
            regsupd_kernel<<<RR, 512>>>(regs + RDR, wproj_w + (size_t)pp * RR * DD * DRR,
                                        wgate_w + (size_t)pp * RR * DD,
                                        wgate_b + (size_t)pp * RR, regs);
            if (ph < PHH - 1) {
                // res update + LN for next phase (fp16)
                fused_ln_kernel<1,0,1><<<NTOK, 256>>>(res, delta, gate, pw, p, nullptr,
                                                      nullptr, nullptr, nullptr, nullptr, nullptr,
                                                      ffn_ln_s + (size_t)(ph + 1) * DD,
                                                      ffn_ln_b + (size_t)(ph + 1) * DD, xnh);
            } else {
                bankcopy_kernel<<<1, RDR>>>(regs, banks, p);
                if (p < PP - 1) {
                    vecmat_split_kernel<<<8, 512>>>(banks, s4_q, nullptr, nullptr, q,
                                                    (p + 1) * RDR, DD, 0);
                    matvec_kernel<<<512, 128>>>(s4_k, q, kq);
                    fused_ln_kernel<1,1,1><<<NTOK, 256>>>(res, delta, gate, pw, p, nullptr,
                                                          s4_ln_s, s4_ln_b, kq, sc, xn,
                                                          ffn_ln_s, ffn_ln_b, xnh);
                } else {
                    vecmat_split_kernel<<<8, 512>>>(banks, m4_q, nullptr, nullptr, q,
                                                    PP * RDR, DD, 0);
                    matvec_kernel<<<512, 128>>>(m4_k, q, kq);
                    fused_ln_kernel<1,1,0><<<NTOK, 256>>>(res, delta, gate, pw, p, nullptr,
                                                          m4_ln_s, m4_ln_b, kq, sc, xn,
                                                          nullptr, nullptr, nullptr);
                }
            }
        }
    }

    // ---- MetaS4 (xn + sc ready) ----
    softmax_kernel<<<BB, 1024>>>(sc);
    wxpart_kernel<<<128, 512>>>(sc, xn, part);
    part_reduce_kernel<<<BB, 512>>>(part, wxb, 32, 1.0f, nullptr);
    for (int b = 0; b < BB; b++) {
        vecmat_split_kernel<<<8, 512>>>(wxb + (size_t)b * DD, m4_v, nullptr, nullptr,
                                        ms1 + (size_t)b * DD, DD, DD, 0);
        vecmat_split_kernel<<<8, 512>>>(ms1 + (size_t)b * DD, m4_out, nullptr, nullptr,
                                        mo + (size_t)b * DD, DD, DD, 0);
    }
    // final: res + mo -> LayerNorm -> d_out (no res writeback)
    fused_ln_kernel<2,1,0><<<NTOK, 256>>>(res, nullptr, nullptr, nullptr, 0, mo,
                                          out_ln_s, out_ln_b, nullptr, nullptr,
                                          (float*)d_out, nullptr, nullptr, nullptr);
}

// round 8
// speedup vs baseline: 5.8486x; 1.0353x over previous
#include <cuda_runtime.h>
#include <cuda_fp16.h>
#include <math.h>
#include <stdint.h>

// ---------------- problem constants ----------------
#define BB 4
#define LL 2048
#define DD 512
#define DRR 256
#define RR 3
#define PP 5
#define PHH 3
#define FF 1536
#define NTOK (BB*LL)            // 8192
#define RDR (RR*DRR)            // 768

// ---------------- device scratch ----------------
__device__ __align__(256) float g_res[NTOK*DD];
__device__ __align__(256) float g_xn[NTOK*DD];
__device__ __align__(256) float g_delta[NTOK*DD];
__device__ __align__(256) float g_sc[NTOK];
__device__ __align__(256) float g_part[128*DD];
__device__ __align__(256) float g_q[DD];
__device__ __align__(256) float g_kq[DD];
__device__ __align__(256) float g_wxm[DD];
__device__ __align__(256) float g_summ[DD];
__device__ __align__(256) float g_regs[RDR];
__device__ __align__(256) float g_gate[DD];
__device__ __align__(256) float g_banks[PP*RDR];
__device__ __align__(256) float g_pw[16];
__device__ __align__(256) float g_wxb[BB*DD];
__device__ __align__(256) float g_ms1[BB*DD];
__device__ __align__(256) float g_mo[BB*DD];

__device__ __align__(256) __half g_xnh[NTOK*DD];
__device__ __align__(256) __half g_hh[NTOK*FF];
__device__ __align__(256) __half g_w1th[PHH*FF*DD];
__device__ __align__(256) __half g_w2th[PHH*DD*FF];

// ---------------- PTX helpers ----------------
__device__ __forceinline__ uint32_t smem_u32(const void* p) {
    return (uint32_t)__cvta_generic_to_shared(p);
}
__device__ __forceinline__ void cpasync16(uint32_t dst, const void* src) {
    asm volatile("cp.async.cg.shared.global [%0], [%1], 16;" :: "r"(dst), "l"(src) : "memory");
}
__device__ __forceinline__ void cp_commit() {
    asm volatile("cp.async.commit_group;" ::: "memory");
}
__device__ __forceinline__ void cp_wait1() {
    asm volatile("cp.async.wait_group 1;" ::: "memory");
}
__device__ __forceinline__ void ldsm4(uint32_t* r, uint32_t addr) {
    asm volatile("ldmatrix.sync.aligned.m8n8.x4.shared.b16 {%0,%1,%2,%3}, [%4];"
                 : "=r"(r[0]), "=r"(r[1]), "=r"(r[2]), "=r"(r[3]) : "r"(addr));
}
__device__ __forceinline__ void mma16816(float* c, const uint32_t* a, uint32_t b0, uint32_t b1) {
    asm volatile(
        "mma.sync.aligned.m16n8k16.row.col.f32.f16.f16.f32 "
        "{%0,%1,%2,%3}, {%4,%5,%6,%7}, {%8,%9}, {%0,%1,%2,%3};"
        : "+f"(c[0]), "+f"(c[1]), "+f"(c[2]), "+f"(c[3])
        : "r"(a[0]), "r"(a[1]), "r"(a[2]), "r"(a[3]), "r"(b0), "r"(b1));
}

// ---------------- fp16 GEMM via mma.sync ----------------
// C[M,N] = A[M,K] @ B^T. fp32 accumulate.
// OUTMODE 0: Cf = acc + bias; also per-CTA column partial sums of acc (no bias)
//            into part[by*512 + col].
// OUTMODE 1: Ch = fp16(gelu(acc+bias)).
// CTA tile 128x128, 256 thr (8 warps: 4m x 2n), kchunk 64,
// 3-stage cp.async pipeline (96KB dyn smem, occ 2), ONE sync per chunk.

#define STAGE_BYTES 32768           // A 16KB + B 16KB
#define NSTAGE 3

template <int OUTMODE>
__global__ void __launch_bounds__(256, 2)
mmagemm_kernel(const __half* __restrict__ Ah, const __half* __restrict__ Bh,
               const float* __restrict__ bias,
               float* __restrict__ Cf, __half* __restrict__ Ch,
               float* __restrict__ part,
               int M, int N, int K) {
    extern __shared__ __align__(128) unsigned char smem[];   // 3 * 32KB

    const int tid  = threadIdx.x;
    const int wid  = tid >> 5;
    const int lane = tid & 31;
    const int n0 = blockIdx.x * 128;
    const int m0 = blockIdx.y * 128;

    const int NIT = K >> 6;             // k64 chunks

    const uint32_t smem_base = smem_u32(smem);

    int lrowA[4]; int lcA[4]; uint32_t ldst[4];
    #pragma unroll
    for (int u = 0; u < 4; u++) {
        int s = tid + u * 256;
        int row = s >> 3, c = s & 7;
        lrowA[u] = row; lcA[u] = c;
        ldst[u] = (uint32_t)(row * 128 + ((c ^ (row & 7)) << 4));
    }

    auto prefetch = [&](int it) {
        const int k0 = it << 6;
        const uint32_t st = smem_base + (uint32_t)(it % NSTAGE) * STAGE_BYTES;
        #pragma unroll
        for (int u = 0; u < 4; u++)
            cpasync16(st + ldst[u], Ah + (size_t)(m0 + lrowA[u]) * K + k0 + lcA[u] * 8);
        #pragma unroll
        for (int u = 0; u < 4; u++)
            cpasync16(st + 16384 + ldst[u], Bh + (size_t)(n0 + lrowA[u]) * K + k0 + lcA[u] * 8);
        cp_commit();
    };

    float acc[2][8][4];
    #pragma unroll
    for (int i = 0; i < 2; i++)
        #pragma unroll
        for (int j = 0; j < 8; j++)
            #pragma unroll
            for (int t = 0; t < 4; t++) acc[i][j][t] = 0.f;

    const int wm = (wid & 3) * 32;
    const int wn = (wid >> 2) * 64;
    const int lrow = lane & 15;
    const int lseg = lane >> 4;

    prefetch(0);
    if (NIT > 1) prefetch(1);

    #pragma unroll 1
    for (int it = 0; it < NIT; it++) {
        cp_wait1();
        __syncthreads();
        if (it + 2 < NIT) prefetch(it + 2);   // slot (it+2)%3 consumed in iter it-1

        const uint32_t st = smem_base + (uint32_t)(it % NSTAGE) * STAGE_BYTES;
        #pragma unroll
        for (int kk = 0; kk < 4; kk++) {
            uint32_t af[2][4];
            #pragma unroll
            for (int i = 0; i < 2; i++) {
                int row = wm + i * 16 + lrow;
                int seg = kk * 2 + lseg;
                ldsm4(af[i], st + (uint32_t)(row * 128 + (((seg ^ (row & 7))) << 4)));
            }
            uint32_t bf[4][4];
            #pragma unroll
            for (int g = 0; g < 4; g++) {
                int row = wn + g * 16 + lrow;
                int seg = kk * 2 + lseg;
                ldsm4(bf[g], st + 16384u + (uint32_t)(row * 128 + (((seg ^ (row & 7))) << 4)));
            }
            #pragma unroll
            for (int i = 0; i < 2; i++)
                #pragma unroll
                for (int j = 0; j < 8; j++) {
                    int g = j >> 1, w = j & 1;
                    mma16816(acc[i][j], af[i], bf[g][w], bf[g][w + 2]);
                }
        }
    }

    // ---- epilogue ----
    const int l4 = lane >> 2;
    const int l2 = (lane & 3) * 2;

    if (OUTMODE == 0) {
        float cs0[8], cs1[8];
        #pragma unroll
        for (int j = 0; j < 8; j++) {
            cs0[j] = acc[0][j][0] + acc[0][j][2] + acc[1][j][0] + acc[1][j][2];
            cs1[j] = acc[0][j][1] + acc[0][j][3] + acc[1][j][1] + acc[1][j][3];
            #pragma unroll
            for (int off = 4; off <= 16; off <<= 1) {
                cs0[j] += __shfl_xor_sync(0xffffffffu, cs0[j], off);
                cs1[j] += __shfl_xor_sync(0xffffffffu, cs1[j], off);
            }
        }
        __syncthreads();                     // mainloop smem reads done before reuse
        float* cs = (float*)smem;
        if (lane < 4) {
            #pragma unroll
            for (int j = 0; j < 8; j++) {
                cs[wid * 64 + j * 8 + lane * 2 + 0] = cs0[j];
                cs[wid * 64 + j * 8 + lane * 2 + 1] = cs1[j];
            }
        }
        __syncthreads();
        if (tid < 128) {
            int ng = tid >> 6, cw = tid & 63;
            float s = cs[(ng * 4 + 0) * 64 + cw] + cs[(ng * 4 + 1) * 64 + cw]
                    + cs[(ng * 4 + 2) * 64 + cw] + cs[(ng * 4 + 3) * 64 + cw];
            part[(size_t)blockIdx.y * 512 + n0 + ng * 64 + cw] = s;
        }
    }

    #pragma unroll
    for (int i = 0; i < 2; i++) {
        #pragma unroll
        for (int j = 0; j < 8; j++) {
            const int col  = n0 + wn + j * 8 + l2;
            const int row0 = m0 + wm + i * 16 + l4;
            const float b0v = bias[col];
            const float b1v = bias[col + 1];
            float v00 = acc[i][j][0] + b0v, v01 = acc[i][j][1] + b1v;
            float v10 = acc[i][j][2] + b0v, v11 = acc[i][j][3] + b1v;
            if (OUTMODE == 0) {
                *(float2*)(Cf + (size_t)row0 * N + col)       = make_float2(v00, v01);
                *(float2*)(Cf + (size_t)(row0 + 8) * N + col) = make_float2(v10, v11);
            } else {
                float vv[4] = {v00, v01, v10, v11};
                unsigned short hh_[4];
                #pragma unroll
                for (int t = 0; t < 4; t++) {
                    float v = vv[t];
                    v = 0.5f * v * (1.0f + erff(v * 0.70710678118654752f));
                    hh_[t] = __half_as_ushort(__float2half_rn(v));
                }
                *(ushort2*)((unsigned short*)Ch + (size_t)row0 * N + col)       = make_ushort2(hh_[0], hh_[1]);
                *(ushort2*)((unsigned short*)Ch + (size_t)(row0 + 8) * N + col) = make_ushort2(hh_[2], hh_[3]);
            }
        }
    }
}

// ---------------- fused residual-update + LayerNorm ----------------
template <int INMODE, int EMIT_XN, int EMIT_XNH>
__global__ void fused_ln_kernel(float* __restrict__ res, const float* __restrict__ delta,
                                const float* __restrict__ gate, const float* __restrict__ pw, int p,
                                const float* __restrict__ mo,
                                const float* __restrict__ sA, const float* __restrict__ bA,
                                const float* __restrict__ kq, float* __restrict__ score,
                                float* __restrict__ xn,
                                const float* __restrict__ sB, const float* __restrict__ bB,
                                __half* __restrict__ xnh) {
    __shared__ float red[256];
    int t = blockIdx.x;
    int tid = threadIdx.x;
    size_t o0 = (size_t)t * DD + tid, o1 = o0 + 256;
    float r0 = res[o0], r1 = res[o1];
    if (INMODE == 1) {
        float w = pw[p];
        r0 += w * gate[tid]       * delta[o0];
        r1 += w * gate[tid + 256] * delta[o1];
        res[o0] = r0; res[o1] = r1;
    } else if (INMODE == 2) {
        int b = t >> 11;
        r0 += mo[(b << 9) + tid];
        r1 += mo[(b << 9) + tid + 256];
    }
    red[tid] = r0 + r1; __syncthreads();
    #pragma unroll
    for (int o = 128; o > 0; o >>= 1) { if (tid < o) red[tid] += red[tid + o]; __syncthreads(); }
    float mean = red[0] * (1.0f / 512.0f);
    __syncthreads();
    float d0 = r0 - mean, d1 = r1 - mean;
    red[tid] = d0 * d0 + d1 * d1; __syncthreads();
    #pragma unroll
    for (int o = 128; o > 0; o >>= 1) { if (tid < o) red[tid] += red[tid + o]; __syncthreads(); }
    float rstd = rsqrtf(red[0] * (1.0f / 512.0f) + 1e-5f);
    __syncthreads();
    if (EMIT_XN) {
        float y0 = d0 * rstd * sA[tid] + bA[tid];
        float y1 = d1 * rstd * sA[tid + 256] + bA[tid + 256];
        xn[o0] = y0; xn[o1] = y1;
        if (kq) {
            red[tid] = y0 * kq[tid] + y1 * kq[tid + 256]; __syncthreads();
            #pragma unroll
            for (int o = 128; o > 0; o >>= 1) { if (tid < o) red[tid] += red[tid + o]; __syncthreads(); }
            if (tid == 0) score[t] = red[0] * 0.044194173824159216f;
        }
    }
    if (EMIT_XNH) {
        float z0 = d0 * rstd * sB[tid] + bB[tid];
        float z1 = d1 * rstd * sB[tid + 256] + bB[tid + 256];
        xnh[o0] = __float2half_rn(z0);
        xnh[o1] = __float2half_rn(z1);
    }
}

// ---------------- gate: summary(from part)+gin matvec+sigmoid, grid 8 x 512 ----------------
__global__ void gate_kernel(const float* __restrict__ part, const float* __restrict__ b2,
                            const float* __restrict__ regs, const float* __restrict__ M,
                            const float* __restrict__ gb, float* __restrict__ gate) {
    __shared__ float ssum[512];
    __shared__ float red[512];
    int tid = threadIdx.x;
    float acc = 0.f;
    #pragma unroll 8
    for (int c = 0; c < 64; c++)
        acc += part[c * 512 + tid];
    ssum[tid] = acc * (1.0f / (float)NTOK) + b2[tid];
    __syncthreads();
    int j = blockIdx.x * 64 + (tid & 63);
    int s = tid >> 6;                   // 8 slices of 160 rows (1280 total)
    float a = 0.f;
    #pragma unroll 8
    for (int d = s * 160; d < s * 160 + 160; d++) {
        float v = (d < RDR) ? regs[d] : ssum[d - RDR];
        a += v * M[(size_t)d * DD + j];
    }
    red[tid] = a; __syncthreads();
    if (tid < 64) {
        float g = 0.f;
        #pragma unroll
        for (int k = 0; k < 8; k++) g += red[k * 64 + tid];
        g += gb[j];
        gate[j] = 1.f / (1.f + expf(-g));
    }
}

// ---------------- regs update: summary(from part) + wg + proj; optional bank write ----------------
__global__ void regsupd_kernel(const float* __restrict__ part, const float* __restrict__ b2,
                               const float* __restrict__ Wp,
                               const float* __restrict__ Wg, const float* __restrict__ bg,
                               float* __restrict__ regs, float* __restrict__ banks) {
    __shared__ float ssum[512];
    __shared__ float red[512];
    __shared__ float shw;
    int r = blockIdx.x;
    int tid = threadIdx.x;
    float acc = 0.f;
    #pragma unroll 8
    for (int c = 0; c < 64; c++)
        acc += part[c * 512 + tid];
    float sv = acc * (1.0f / (float)NTOK) + b2[tid];
    ssum[tid] = sv;
    red[tid] = sv * Wg[(size_t)r * DD + tid];
    __syncthreads();
    #pragma unroll
    for (int o = 256; o > 0; o >>= 1) { if (tid < o) red[tid] += red[tid + o]; __syncthreads(); }
    if (tid == 0) shw = 1.f / (1.f + expf(-(red[0] + bg[r])));
    __syncthreads();
    int k = tid & 255, s = tid >> 8;
    const float* W = Wp + (size_t)r * DD * DRR;
    float a = 0.f;
    #pragma unroll 16
    for (int d = s * 256; d < (s + 1) * 256; d++)
        a += ssum[d] * W[(size_t)d * DRR + k];
    red[tid] = a; __syncthreads();
    if (tid < 256) {
        float nv = regs[r * DRR + k] + shw * (red[k] + red[k + 256]);
        regs[r * DRR + k] = nv;
        if (banks) banks[r * DRR + k] = nv;
    }
}

// ---------------- k-split vec @ mat ----------------
__global__ void vecmat_split_kernel(const float* __restrict__ v, const float* __restrict__ M,
                                    const float* __restrict__ bias, const float* __restrict__ init,
                                    float* __restrict__ out, int nrow, int ncol, int act) {
    __shared__ float red[512];
    int tid = threadIdx.x;
    int j = blockIdx.x * 64 + (tid & 63);
    int s = tid >> 6;
    int sl = nrow >> 3;
    float acc = 0.f;
    #pragma unroll 16
    for (int d = s * sl; d < (s + 1) * sl; d++)
        acc += v[d] * M[(size_t)d * ncol + j];
    red[tid] = acc; __syncthreads();
    if (tid < 64) {
        float a = 0.f;
        #pragma unroll
        for (int k = 0; k < 8; k++) a += red[k * 64 + tid];
        if (bias) a += bias[j];
        if (init) a += init[j];
        if (act == 1) a = 1.f / (1.f + expf(-a));
        out[j] = a;
    }
}

// ---------------- other small kernels ----------------

__global__ void transpose_half_kernel(const float* __restrict__ in,
                                      __half* __restrict__ oh,
                                      int Rr, int Cc) {
    __shared__ float t[32][33];
    int r = blockIdx.y * 32 + threadIdx.y;
    int c = blockIdx.x * 32 + threadIdx.x;
    t[threadIdx.y][threadIdx.x] = in[(size_t)r * Cc + c];
    __syncthreads();
    int orow = blockIdx.x * 32 + threadIdx.y;
    int ocol = blockIdx.y * 32 + threadIdx.x;
    oh[(size_t)orow * Rr + ocol] = __float2half_rn(t[threadIdx.x][threadIdx.y]);
}

__global__ void copy4_kernel(const float4* __restrict__ src, float4* __restrict__ dst) {
    size_t i = (size_t)blockIdx.x * blockDim.x + threadIdx.x;
    dst[i] = src[i];
}

__global__ void passw_kernel(const float* __restrict__ reg_init,
                             const float* __restrict__ W,
                             const float* __restrict__ b,
                             float* __restrict__ pw) {
    __shared__ float red[256];
    int p = blockIdx.x;
    int tid = threadIdx.x;
    float acc = 0.f;
    for (int i = tid; i < PP * RDR; i += 256)
        acc += reg_init[i % RDR] * W[i * PP + p];
    red[tid] = acc; __syncthreads();
    #pragma unroll
    for (int o = 128; o > 0; o >>= 1) { if (tid < o) red[tid] += red[tid + o]; __syncthreads(); }
    if (tid == 0) pw[p] = 1.f / (1.f + expf(-(red[0] + b[p])));
}

__global__ void matvec_kernel(const float* __restrict__ M,
                              const float* __restrict__ v,
                              float* __restrict__ out) {
    __shared__ float red[128];
    int r = blockIdx.x;
    int tid = threadIdx.x;
    float acc = 0.f;
    #pragma unroll
    for (int j = tid; j < DD; j += 128)
        acc += M[(size_t)r * DD + j] * v[j];
    red[tid] = acc; __syncthreads();
    for (int o = 64; o > 0; o >>= 1) {
        if (tid < o) red[tid] += red[tid + o];
        __syncthreads();
    }
    if (tid == 0) out[r] = red[0];
}

__global__ void softmax_kernel(float* __restrict__ sc) {
    __shared__ float red[1024];
    int b = blockIdx.x;
    float* p = sc + (size_t)b * LL;
    int tid = threadIdx.x;
    float v0 = p[tid], v1 = p[tid + 1024];
    red[tid] = fmaxf(v0, v1); __syncthreads();
    #pragma unroll
    for (int o = 512; o > 0; o >>= 1) { if (tid < o) red[tid] = fmaxf(red[tid], red[tid + o]); __syncthreads(); }
    float mx = red[0];
    __syncthreads();
    float e0 = expf(v0 - mx), e1 = expf(v1 - mx);
    red[tid] = e0 + e1; __syncthreads();
    #pragma unroll
    for (int o = 512; o > 0; o >>= 1) { if (tid < o) red[tid] += red[tid + o]; __syncthreads(); }
    float inv = 1.f / red[0];
    p[tid] = e0 * inv;
    p[tid + 1024] = e1 * inv;
}

__global__ void wxpart_kernel(const float* __restrict__ a, const float* __restrict__ xn,
                              float* __restrict__ part) {
    int d = threadIdx.x;
    int blk = blockIdx.x;
    int row0 = blk * 64;
    float acc = 0.f;
    #pragma unroll 8
    for (int r = row0; r < row0 + 64; r++)
        acc += a[r] * xn[(size_t)r * DD + d];
    part[(size_t)blk * DD + d] = acc;
}

__global__ void part_reduce_kernel(const float* __restrict__ part, float* __restrict__ out,
                                   int nchunk, float scale, const float* __restrict__ bias) {
    int d = threadIdx.x;
    int g = blockIdx.x;
    const float* p = part + (size_t)g * nchunk * DD;
    float acc = 0.f;
    #pragma unroll 8
    for (int c = 0; c < nchunk; c++)
        acc += p[(size_t)c * DD + d];
    acc *= scale;
    if (bias) acc += bias[d];
    out[(size_t)g * DD + d] = acc;
}

// ---------------- host orchestration ----------------

extern "C" void kernel_launch(void* const* d_in, const int* in_sizes, int n_in,
                              void* d_out, int out_size) {
    const float* x        = (const float*)d_in[0];
    const float* reg_init = (const float*)d_in[1];
    const float* ffn_ln_s = (const float*)d_in[2];
    const float* ffn_ln_b = (const float*)d_in[3];
    const float* ffn_w1   = (const float*)d_in[4];
    const float* ffn_b1   = (const float*)d_in[5];
    const float* ffn_w2   = (const float*)d_in[6];
    const float* ffn_b2   = (const float*)d_in[7];
    const float* gate_w   = (const float*)d_in[8];
    const float* gate_b   = (const float*)d_in[9];
    const float* wproj_w  = (const float*)d_in[10];
    const float* wgate_w  = (const float*)d_in[11];
    const float* wgate_b  = (const float*)d_in[12];
    const float* s4_q     = (const float*)d_in[13];
    const float* s4_k     = (const float*)d_in[14];
    const float* s4_v     = (const float*)d_in[15];
    const float* s4_sum   = (const float*)d_in[16];
    const float* s4_ln_s  = (const float*)d_in[17];
    const float* s4_ln_b  = (const float*)d_in[18];
    const float* ms3_w    = (const float*)d_in[19];
    const float* ms3_b    = (const float*)d_in[20];
    const float* m4_q     = (const float*)d_in[21];
    const float* m4_k     = (const float*)d_in[22];
    const float* m4_v     = (const float*)d_in[23];
    const float* m4_out   = (const float*)d_in[24];
    const float* m4_ln_s  = (const float*)d_in[25];
    const float* m4_ln_b  = (const float*)d_in[26];
    const float* out_ln_s = (const float*)d_in[27];
    const float* out_ln_b = (const float*)d_in[28];

    float *res, *xn, *delta, *sc, *part, *q, *kq, *wxm, *summ, *regs, *gate;
    float *banks, *pw, *wxb, *ms1, *mo;
    __half *xnh, *hh, *w1th, *w2th;
    cudaGetSymbolAddress((void**)&res,   g_res);
    cudaGetSymbolAddress((void**)&xn,    g_xn);
    cudaGetSymbolAddress((void**)&delta, g_delta);
    cudaGetSymbolAddress((void**)&sc,    g_sc);
    cudaGetSymbolAddress((void**)&part,  g_part);
    cudaGetSymbolAddress((void**)&q,     g_q);
    cudaGetSymbolAddress((void**)&kq,    g_kq);
    cudaGetSymbolAddress((void**)&wxm,   g_wxm);
    cudaGetSymbolAddress((void**)&summ,  g_summ);
    cudaGetSymbolAddress((void**)&regs,  g_regs);
    cudaGetSymbolAddress((void**)&gate,  g_gate);
    cudaGetSymbolAddress((void**)&banks, g_banks);
    cudaGetSymbolAddress((void**)&pw,    g_pw);
    cudaGetSymbolAddress((void**)&wxb,   g_wxb);
    cudaGetSymbolAddress((void**)&ms1,   g_ms1);
    cudaGetSymbolAddress((void**)&mo,    g_mo);
    cudaGetSymbolAddress((void**)&xnh,   g_xnh);
    cudaGetSymbolAddress((void**)&hh,    g_hh);
    cudaGetSymbolAddress((void**)&w1th,  g_w1th);
    cudaGetSymbolAddress((void**)&w2th,  g_w2th);

    const int ELEM = NTOK * DD;

    cudaFuncSetAttribute(mmagemm_kernel<0>, cudaFuncAttributeMaxDynamicSharedMemorySize, NSTAGE * STAGE_BYTES);
    cudaFuncSetAttribute(mmagemm_kernel<1>, cudaFuncAttributeMaxDynamicSharedMemorySize, NSTAGE * STAGE_BYTES);

    // weight transpose -> fp16
    for (int ph = 0; ph < PHH; ph++) {
        dim3 blk(32, 32);
        dim3 g1(FF / 32, DD / 32);
        transpose_half_kernel<<<g1, blk>>>(ffn_w1 + (size_t)ph * DD * FF,
                                           w1th + (size_t)ph * FF * DD, DD, FF);
        dim3 g2(DD / 32, FF / 32);
        transpose_half_kernel<<<g2, blk>>>(ffn_w2 + (size_t)ph * FF * DD,
                                           w2th + (size_t)ph * DD * FF, FF, DD);
    }

    copy4_kernel<<<ELEM / 4 / 256, 256>>>((const float4*)x, (float4*)res);
    passw_kernel<<<PP, 256>>>(reg_init, ms3_w, ms3_b, pw);

    // p=0 S4 prep: q=0, kq, fused LN emitting xn+score and xnh(ph0)
    vecmat_split_kernel<<<8, 512>>>(banks, s4_q, nullptr, nullptr, q, 0, DD, 0);
    matvec_kernel<<<512, 128>>>(s4_k, q, kq);
    fused_ln_kernel<0,1,1><<<NTOK, 256>>>(res, nullptr, nullptr, nullptr, 0, nullptr,
                                          s4_ln_s, s4_ln_b, kq, sc, xn,
                                          ffn_ln_s, ffn_ln_b, xnh);

    for (int p = 0; p < PP; p++) {
        // ---- S4 read (collapsed attention; xn+sc ready) ----
        softmax_kernel<<<BB, 1024>>>(sc);
        wxpart_kernel<<<128, 512>>>(sc, xn, part);
        part_reduce_kernel<<<1, 512>>>(part, wxm, 128, 1.0f / BB, nullptr);
        vecmat_split_kernel<<<8, 512>>>(wxm, s4_v, nullptr, nullptr, summ, DD, DD, 0);
        vecmat_split_kernel<<<12, 512>>>(summ, s4_sum, nullptr, reg_init, regs, DD, RDR, 0);

        for (int ph = 0; ph < PHH; ph++) {
            const int pp = p * PHH + ph;
            {
                dim3 grid(FF / 128, NTOK / 128);
                mmagemm_kernel<1><<<grid, 256, NSTAGE * STAGE_BYTES>>>(
                    xnh, w1th + (size_t)ph * FF * DD,
                    ffn_b1 + (size_t)ph * FF, nullptr, hh, nullptr, NTOK, FF, DD);
            }
            {
                dim3 grid(DD / 128, NTOK / 128);
                mmagemm_kernel<0><<<grid, 256, NSTAGE * STAGE_BYTES>>>(
                    hh, w2th + (size_t)ph * DD * FF,
                    ffn_b2 + (size_t)ph * DD, delta, nullptr, part, NTOK, DD, FF);
            }
            // gate = sigmoid([regs|summary] @ gate_w + gate_b) (summary from part)
            gate_kernel<<<8, 512>>>(part, ffn_b2 + (size_t)ph * DD, regs,
                                    gate_w + (size_t)pp * (RDR + DD) * DD,
                                    gate_b + (size_t)pp * DD, gate);
            // register update (summary + wg fused; bank write at phase end)
            regsupd_kernel<<<RR, 512>>>(part, ffn_b2 + (size_t)ph * DD,
                                        wproj_w + (size_t)pp * RR * DD * DRR,
                                        wgate_w + (size_t)pp * RR * DD,
                                        wgate_b + (size_t)pp * RR, regs,
                                        (ph == PHH - 1) ? (banks + (size_t)p * RDR) : nullptr);
            if (ph < PHH - 1) {
                fused_ln_kernel<1,0,1><<<NTOK, 256>>>(res, delta, gate, pw, p, nullptr,
                                                      nullptr, nullptr, nullptr, nullptr, nullptr,
                                                      ffn_ln_s + (size_t)(ph + 1) * DD,
                                                      ffn_ln_b + (size_t)(ph + 1) * DD, xnh);
            } else {
                if (p < PP - 1) {
                    vecmat_split_kernel<<<8, 512>>>(banks, s4_q, nullptr, nullptr, q,
                                                    (p + 1) * RDR, DD, 0);
                    matvec_kernel<<<512, 128>>>(s4_k, q, kq);
                    fused_ln_kernel<1,1,1><<<NTOK, 256>>>(res, delta, gate, pw, p, nullptr,
                                                          s4_ln_s, s4_ln_b, kq, sc, xn,
                                                          ffn_ln_s, ffn_ln_b, xnh);
                } else {
                    vecmat_split_kernel<<<8, 512>>>(banks, m4_q, nullptr, nullptr, q,
                                                    PP * RDR, DD, 0);
                    matvec_kernel<<<512, 128>>>(m4_k, q, kq);
                    fused_ln_kernel<1,1,0><<<NTOK, 256>>>(res, delta, gate, pw, p, nullptr,
                                                          m4_ln_s, m4_ln_b, kq, sc, xn,
                                                          nullptr, nullptr, nullptr);
                }
            }
        }
    }

    // ---- MetaS4 ----
    softmax_kernel<<<BB, 1024>>>(sc);
    wxpart_kernel<<<128, 512>>>(sc, xn, part);
    part_reduce_kernel<<<BB, 512>>>(part, wxb, 32, 1.0f, nullptr);
    for (int b = 0; b < BB; b++) {
        vecmat_split_kernel<<<8, 512>>>(wxb + (size_t)b * DD, m4_v, nullptr, nullptr,
                                        ms1 + (size_t)b * DD, DD, DD, 0);
        vecmat_split_kernel<<<8, 512>>>(ms1 + (size_t)b * DD, m4_out, nullptr, nullptr,
                                        mo + (size_t)b * DD, DD, DD, 0);
    }
    fused_ln_kernel<2,1,0><<<NTOK, 256>>>(res, nullptr, nullptr, nullptr, 0, mo,
                                          out_ln_s, out_ln_b, nullptr, nullptr,
                                          (float*)d_out, nullptr, nullptr, nullptr);
}